// round 10
// baseline (speedup 1.0000x reference)
#include <cuda_runtime.h>
#include <cuda_bf16.h>
#include <cuda_fp16.h>

// Problem constants
#define Bb 2
#define Ss 2048
#define Ee 1024
#define Hh 16
#define Dd 64
#define SCALE (1.0f/32.0f)   // 1/sqrt(E)
#define NSPLIT 2             // flash key-splits

typedef __nv_bfloat16 bf;

// ---------------------------------------------------------------------------
// Scratch (device globals; allocation inside kernel_launch is forbidden)
// ---------------------------------------------------------------------------
__device__ unsigned char g_q8[(size_t)Bb*Hh*Ss*Dd];  // e4m3 [b,h,s,d]
__device__ unsigned char g_k8[(size_t)Bb*Hh*Ss*Dd];  // e4m3 [b,h,s,d] (d-contig!)
__device__ bf    g_v  [(size_t)Bb*Hh*Ss*Dd];         // bf16 [b,h,s,d]
__device__ float g_sk [(size_t)Bb*Hh*Ss];            // 0.5*SCALE*||k8||^2
__device__ float g_po [(size_t)NSPLIT*Bb*Hh*Ss*Dd];  // unnormalized partial out
__device__ float g_l  [(size_t)NSPLIT*Bb*Hh*Ss];     // partial softmax denoms

// ---------------------------------------------------------------------------
// Helpers
// ---------------------------------------------------------------------------
__device__ __forceinline__ unsigned s2u(const void* p) {
    return (unsigned)__cvta_generic_to_shared(p);
}
__device__ __forceinline__ unsigned f22bf(float x, float y) {
    __nv_bfloat162 h = __floats2bfloat162_rn(x, y);
    return *(unsigned*)&h;
}
// pack (v0 -> low byte, v1 -> high byte) as e4m3x2
__device__ __forceinline__ unsigned short f22e4(float v0, float v1) {
    unsigned short r;
    asm("cvt.rn.satfinite.e4m3x2.f32 %0, %1, %2;" : "=h"(r) : "f"(v1), "f"(v0));
    return r;
}
__device__ __forceinline__ float2 e4x2f(unsigned short h) {
    unsigned r;
    asm("cvt.rn.f16x2.e4m3x2 %0, %1;" : "=r"(r) : "h"(h));
    __half2 hh = *(__half2*)&r;
    return __half22float2(hh);
}
// sum of squares of a 64-byte e4m3 row (16B-aligned)
__device__ __forceinline__ float row_sumsq_fp8(const unsigned char* p) {
    float acc = 0.f;
    #pragma unroll
    for (int i = 0; i < 4; i++) {
        uint4 w = *(const uint4*)(p + i*16);
        unsigned arr[4] = {w.x, w.y, w.z, w.w};
        #pragma unroll
        for (int j = 0; j < 4; j++) {
            float2 f0 = e4x2f((unsigned short)(arr[j] & 0xffffu));
            float2 f1 = e4x2f((unsigned short)(arr[j] >> 16));
            acc = fmaf(f0.x, f0.x, acc); acc = fmaf(f0.y, f0.y, acc);
            acc = fmaf(f1.x, f1.x, acc); acc = fmaf(f1.y, f1.y, acc);
        }
    }
    return acc;
}
__device__ __forceinline__ void mma_bf16(float* c, const unsigned* a, const unsigned* b) {
    asm volatile(
        "mma.sync.aligned.m16n8k16.row.col.f32.bf16.bf16.f32 "
        "{%0,%1,%2,%3}, {%4,%5,%6,%7}, {%8,%9}, {%0,%1,%2,%3};"
        : "+f"(c[0]), "+f"(c[1]), "+f"(c[2]), "+f"(c[3])
        : "r"(a[0]), "r"(a[1]), "r"(a[2]), "r"(a[3]), "r"(b[0]), "r"(b[1]));
}
__device__ __forceinline__ void mma_e4(float* c, const unsigned* a, const unsigned* b) {
    asm volatile(
        "mma.sync.aligned.m16n8k32.row.col.f32.e4m3.e4m3.f32 "
        "{%0,%1,%2,%3}, {%4,%5,%6,%7}, {%8,%9}, {%0,%1,%2,%3};"
        : "+f"(c[0]), "+f"(c[1]), "+f"(c[2]), "+f"(c[3])
        : "r"(a[0]), "r"(a[1]), "r"(a[2]), "r"(a[3]), "r"(b[0]), "r"(b[1]));
}
__device__ __forceinline__ void ldmA(unsigned* a, unsigned saddr) {
    asm volatile("ldmatrix.sync.aligned.m8n8.x4.shared.b16 {%0,%1,%2,%3}, [%4];"
        : "=r"(a[0]), "=r"(a[1]), "=r"(a[2]), "=r"(a[3]) : "r"(saddr));
}
__device__ __forceinline__ void ldmB4(unsigned* b, unsigned saddr) {
    asm volatile("ldmatrix.sync.aligned.m8n8.x4.trans.shared.b16 {%0,%1,%2,%3}, [%4];"
        : "=r"(b[0]), "=r"(b[1]), "=r"(b[2]), "=r"(b[3]) : "r"(saddr));
}
__device__ __forceinline__ void cp16(unsigned dst, const void* src) {
    asm volatile("cp.async.cg.shared.global [%0], [%1], 16;" :: "r"(dst), "l"(src));
}
#define CP_COMMIT() asm volatile("cp.async.commit_group;")
#define CP_WAIT0()  asm volatile("cp.async.wait_group 0;")

// ---------------------------------------------------------------------------
// Kernel 1: fused QKV projection, bf16 m16n8k16 mma (tcgen05 unavailable on
// this harness's sm_100 ptxas target).  q/k outputs -> e4m3 [b,h,s,d];
// v -> bf16.  Block tile 128x128, K-chunk 32, double-buffered + reg prefetch.
// ---------------------------------------------------------------------------
__global__ __launch_bounds__(256, 2) void proj_kernel(
    const float* __restrict__ Xq, const float* __restrict__ Xk, const float* __restrict__ Xv,
    const float* __restrict__ Wq, const float* __restrict__ Wk, const float* __restrict__ Wv,
    const float* __restrict__ Bq, const float* __restrict__ Bk, const float* __restrict__ Bv)
{
    const int z = blockIdx.z;
    const float* X    = (z==0) ? Xq : ((z==1) ? Xk : Xv);
    const float* W    = (z==0) ? Wq : ((z==1) ? Wk : Wv);
    const float* bias = (z==0) ? Bq : ((z==1) ? Bk : Bv);

    __shared__ bf Xs[2][128][40];   // [buf][m][k], pad 8
    __shared__ bf Ws[2][32][136];   // [buf][k][n], pad 8

    const int tid  = threadIdx.x;
    const int wid  = tid >> 5, lane = tid & 31;
    const int g    = lane >> 2, qd = lane & 3;
    const int wm   = (wid & 1) * 64;
    const int wn   = (wid >> 1) * 32;
    const int m0   = blockIdx.x * 128;
    const int n0   = blockIdx.y * 128;

    const int arow_l = (lane & 7) + ((lane >> 3) & 1) * 8;
    const int acol_l = (lane >> 4) * 8;
    const int brow_l = (lane & 7) + ((lane >> 3) & 1) * 8;
    const int bcol_l = (lane >> 4) * 8;

    const int xr_r  = tid >> 3,  xr_c = (tid & 7) << 2;
    const int wr_k  = tid >> 5,  wr_c = (tid & 31) << 2;
    const int wn_h  = (n0 + wr_c) >> 6, wn_d = (n0 + wr_c) & 63;

    uint2 xr[4], wr[4];
    auto prefetch = [&](int k0) {
        #pragma unroll
        for (int u = 0; u < 4; u++) {
            float4 xv = *(const float4*)(X + (size_t)(m0 + xr_r + u*32) * Ee + k0 + xr_c);
            xr[u] = make_uint2(f22bf(xv.x, xv.y), f22bf(xv.z, xv.w));
            float4 wv = *(const float4*)(W + (size_t)wn_h * (Ee*Dd)
                                           + (size_t)(k0 + wr_k + u*8) * Dd + wn_d);
            wr[u] = make_uint2(f22bf(wv.x, wv.y), f22bf(wv.z, wv.w));
        }
    };

    float acc[4][4][4];
    #pragma unroll
    for (int mi = 0; mi < 4; mi++)
        #pragma unroll
        for (int nj = 0; nj < 4; nj++)
            #pragma unroll
            for (int r = 0; r < 4; r++) acc[mi][nj][r] = 0.f;

    prefetch(0);

    for (int k0 = 0; k0 < Ee; k0 += 32) {
        const int buf = (k0 >> 5) & 1;
        #pragma unroll
        for (int u = 0; u < 4; u++) {
            *(uint2*)&Xs[buf][xr_r + u*32][xr_c] = xr[u];
            *(uint2*)&Ws[buf][wr_k + u*8][wr_c] = wr[u];
        }
        __syncthreads();
        if (k0 + 32 < Ee) prefetch(k0 + 32);

        #pragma unroll
        for (int ks = 0; ks < 2; ks++) {
            unsigned a[4][4], b[2][4];
            #pragma unroll
            for (int mi = 0; mi < 4; mi++)
                ldmA(a[mi], s2u(&Xs[buf][wm + mi*16 + arow_l][ks*16 + acol_l]));
            #pragma unroll
            for (int p = 0; p < 2; p++)
                ldmB4(b[p], s2u(&Ws[buf][ks*16 + brow_l][wn + p*16 + bcol_l]));
            #pragma unroll
            for (int mi = 0; mi < 4; mi++)
                #pragma unroll
                for (int p = 0; p < 2; p++) {
                    mma_bf16(acc[mi][2*p    ], a[mi], &b[p][0]);
                    mma_bf16(acc[mi][2*p + 1], a[mi], &b[p][2]);
                }
        }
    }

    // Epilogue: +bias; q/k -> e4m3, v -> bf16 (all [b,h,s,d])
    #pragma unroll
    for (int mi = 0; mi < 4; mi++) {
        #pragma unroll
        for (int half = 0; half < 2; half++) {
            int m = m0 + wm + mi*16 + g + half*8;
            int bb = m >> 11, s = m & 2047;
            #pragma unroll
            for (int nj = 0; nj < 4; nj++) {
                int n = n0 + wn + nj*8 + 2*qd;
                int h = n >> 6, d = n & 63;
                float v0 = acc[mi][nj][half*2 + 0] + bias[h*Dd + d];
                float v1 = acc[mi][nj][half*2 + 1] + bias[h*Dd + d + 1];
                size_t bh = (size_t)bb * Hh + h;
                if (z == 2) {
                    *(unsigned*)&g_v[(bh*Ss + s)*Dd + d] = f22bf(v0, v1);
                } else {
                    unsigned char* out8 = (z == 0) ? g_q8 : g_k8;
                    *(unsigned short*)&out8[(bh*Ss + s)*Dd + d] = f22e4(v0, v1);
                }
            }
        }
    }
}

// ---------------------------------------------------------------------------
// Kernel 2: g_sk = 0.5*SCALE*||k8||^2 from the SAME e4m3 k the mma consumes
// (keeps score = -0.5*||q8-k8||^2*SCALE <= 0 exactly -> exp never overflows).
// ---------------------------------------------------------------------------
__global__ __launch_bounds__(256) void knorm_kernel()
{
    int idx = blockIdx.x * 256 + threadIdx.x;   // = bh*Ss + s
    const unsigned char* kp = g_k8 + (size_t)idx * Dd;
    g_sk[idx] = 0.5f * SCALE * row_sumsq_fp8(kp);
}

// ---------------------------------------------------------------------------
// Kernel 3: flash attention.  Scores: e4m3 m16n8k32 (HALF the mma count).
// PV: bf16 m16n8k16.  Fixed-max softmax, split-K(2), unnormalized partials.
// K8 smem [key][d] pitch 80B (B-frag via plain non-trans ldmatrix.x4 —
// byte-extension of the bf16 pattern).  Q8 A-frags in regs.
// ---------------------------------------------------------------------------
__global__ __launch_bounds__(128) void flash_kernel()
{
    __shared__ __align__(16) unsigned char smbuf[32768];
    unsigned char* K8s[2] = { smbuf,          smbuf + 5120  };  // [64][80] bytes
    bf* Vs[2] = { (bf*)(smbuf + 10240), (bf*)(smbuf + 19456) }; // [64][72]
    float* sks = (float*)(smbuf + 28672);                       // [1024]

    const int bh = blockIdx.y;
    const int q0 = blockIdx.x * 64;
    const int ksp = blockIdx.z;
    const int kbase = ksp * (Ss / NSPLIT);
    const int tid = threadIdx.x;
    const int wid = tid >> 5, lane = tid & 31;
    const int g = lane >> 2, qd = lane & 3;

    const unsigned char* Qg8 = g_q8 + ((size_t)bh * Ss + q0) * Dd;
    const unsigned char* Kg8 = g_k8 + (size_t)bh * Ss * Dd;
    const bf* Vg   = g_v  + (size_t)bh * Ss * Dd;
    const float* skg = g_sk + (size_t)bh * Ss + kbase;

    const int arow_l = (lane & 7) + ((lane >> 3) & 1) * 8;
    const int acol8  = (lane >> 4) * 16;                        // byte col for A
    const int brow8  = (lane & 7) + ((lane >> 4) << 3);         // key row for fp8 B
    const int bcol8b = ((lane >> 3) & 1) * 16;                  // byte col for fp8 B
    const int vrow_l = (lane & 7) + ((lane >> 3) & 1) * 8;      // bf16 V rows
    const int vcol_l = (lane >> 4) * 8;
    const int wrow = wid * 16;
    const int crow = wrow + g;

    const int ld_r  = tid >> 3;
    const int ld_c8 = (tid & 7) << 3;

    // ---- Prologue: Q8 tile -> staging (K8s region) -> A regs; sk row ----
    {
        unsigned char* Qst = K8s[0];       // 64*80 = 5120 B
        #pragma unroll
        for (int u = 0; u < 2; u++) {
            int idx = u * 128 + tid;
            int r = idx >> 2, c16 = (idx & 3) * 16;
            *(uint4*)(Qst + r*80 + c16) = *(const uint4*)(Qg8 + (size_t)r * Dd + c16);
        }
        #pragma unroll
        for (int u = 0; u < 2; u++) {
            int idx = u * 128 + tid;
            *(float4*)&sks[idx*4] = *(const float4*)(skg + idx*4);
        }
        __syncthreads();
    }
    unsigned qa[2][4];
    #pragma unroll
    for (int t = 0; t < 2; t++)
        ldmA(qa[t], s2u(K8s[0] + (wrow + arow_l)*80 + t*32 + acol8));

    // row constants: 0.5*SCALE*||q8||^2 (same fp8 q the mma consumes)
    float sq0 = 0.5f * SCALE * row_sumsq_fp8(K8s[0] + crow*80);
    float sq1 = 0.5f * SCALE * row_sumsq_fp8(K8s[0] + (crow+8)*80);
    __syncthreads();   // Q staging dead; cp.async may overwrite

    auto issue_loads = [&](int buf, int k0) {
        const unsigned char* Ksrc = Kg8 + (size_t)k0 * Dd;
        #pragma unroll
        for (int u = 0; u < 2; u++) {
            int idx = u * 128 + tid;
            int r = idx >> 2, c16 = (idx & 3) * 16;
            cp16(s2u(K8s[buf] + r*80 + c16), Ksrc + (size_t)r * Dd + c16);
        }
        #pragma unroll
        for (int u = 0; u < 4; u++) {
            int r = ld_r + u*16;
            cp16(s2u(&Vs[buf][r*72 + ld_c8]), Vg + (size_t)(k0 + r) * Dd + ld_c8);
        }
        CP_COMMIT();
    };
    issue_loads(0, kbase);

    float l0 = 0.f, l1 = 0.f;
    float oacc[8][4];
    #pragma unroll
    for (int j = 0; j < 8; j++)
        #pragma unroll
        for (int r = 0; r < 4; r++) oacc[j][r] = 0.f;

    const int NIT = (Ss / NSPLIT) / 64;   // 16
    for (int it = 0; it < NIT; it++) {
        const int k0 = kbase + it * 64;
        const int buf = it & 1;
        CP_WAIT0();
        __syncthreads();
        if (it + 1 < NIT) issue_loads(buf ^ 1, k0 + 64);

        // ---- scores: fp8 mma, 16 per iter (was 32) ----
        float sc[8][4];
        #pragma unroll
        for (int j = 0; j < 8; j++)
            #pragma unroll
            for (int r = 0; r < 4; r++) sc[j][r] = 0.f;

        #pragma unroll
        for (int t = 0; t < 2; t++) {
            #pragma unroll
            for (int p = 0; p < 4; p++) {
                unsigned b[4];
                ldmA(b, s2u(K8s[buf] + (p*16 + brow8)*80 + t*32 + bcol8b));
                mma_e4(sc[2*p    ], qa[t], &b[0]);
                mma_e4(sc[2*p + 1], qa[t], &b[2]);
            }
        }

        // ---- exact softmax, fixed max 0 ----
        #pragma unroll
        for (int j = 0; j < 8; j++) {
            #pragma unroll
            for (int c = 0; c < 2; c++) {
                float skc = sks[it*64 + j*8 + 2*qd + c];
                float p0 = __expf(fmaf(sc[j][c],   SCALE, -skc) - sq0);
                float p1 = __expf(fmaf(sc[j][2+c], SCALE, -skc) - sq1);
                sc[j][c]   = p0; l0 += p0;
                sc[j][2+c] = p1; l1 += p1;
            }
        }

        // ---- PV: bf16, P straight from registers ----
        #pragma unroll
        for (int t = 0; t < 4; t++) {
            unsigned a[4];
            a[0] = f22bf(sc[2*t  ][0], sc[2*t  ][1]);
            a[1] = f22bf(sc[2*t  ][2], sc[2*t  ][3]);
            a[2] = f22bf(sc[2*t+1][0], sc[2*t+1][1]);
            a[3] = f22bf(sc[2*t+1][2], sc[2*t+1][3]);
            #pragma unroll
            for (int p = 0; p < 4; p++) {
                unsigned b[4];
                ldmB4(b, s2u(&Vs[buf][(t*16 + vrow_l)*72 + p*16 + vcol_l]));
                mma_bf16(oacc[2*p    ], a, &b[0]);
                mma_bf16(oacc[2*p + 1], a, &b[2]);
            }
        }
    }

    l0 += __shfl_xor_sync(0xffffffffu, l0, 1);
    l0 += __shfl_xor_sync(0xffffffffu, l0, 2);
    l1 += __shfl_xor_sync(0xffffffffu, l1, 1);
    l1 += __shfl_xor_sync(0xffffffffu, l1, 2);

    // Epilogue: UNNORMALIZED partial out + l (combined in ln_kernel)
    const int s0 = q0 + crow, s1 = s0 + 8;
    float* po = g_po + ((size_t)ksp * (Bb*Hh) + bh) * (Ss * Dd);
    #pragma unroll
    for (int j = 0; j < 8; j++) {
        int col = j*8 + 2*qd;
        *(float2*)&po[(size_t)s0 * Dd + col] = make_float2(oacc[j][0], oacc[j][1]);
        *(float2*)&po[(size_t)s1 * Dd + col] = make_float2(oacc[j][2], oacc[j][3]);
    }
    if (qd == 0) {
        float* pl = g_l + ((size_t)ksp * (Bb*Hh) + bh) * Ss;
        pl[s0] = l0;
        pl[s1] = l1;
    }
}

// ---------------------------------------------------------------------------
// Kernel 4: split-combine + residual add + custom LayerNorm.
// ---------------------------------------------------------------------------
__global__ __launch_bounds__(256) void ln_kernel(
    const float* __restrict__ resid, const float* __restrict__ gamma,
    const float* __restrict__ beta, float* __restrict__ out)
{
    const int row = blockIdx.x;            // b*2048 + s
    const int b = row >> 11, s = row & 2047;
    const int tid = threadIdx.x;
    const int h = tid >> 4;
    const int dv4 = (tid & 15) << 2;
    const size_t bh = (size_t)b * Hh + h;

    const float* po0 = g_po + (bh                 ) * (Ss * Dd) + (size_t)s * Dd + dv4;
    const float* po1 = g_po + ((size_t)Bb*Hh + bh ) * (Ss * Dd) + (size_t)s * Dd + dv4;
    float linv = 1.0f / (g_l[bh * Ss + s] + g_l[((size_t)Bb*Hh + bh) * Ss + s]);

    float4 a0 = *(const float4*)po0;
    float4 a1 = *(const float4*)po1;
    float4 r  = *(const float4*)(resid + (size_t)row * Ee + tid*4);
    float x0 = (a0.x + a1.x) * linv + r.x;
    float x1 = (a0.y + a1.y) * linv + r.y;
    float x2 = (a0.z + a1.z) * linv + r.z;
    float x3 = (a0.w + a1.w) * linv + r.w;

    float sum = x0 + x1 + x2 + x3;
    float sq  = x0*x0 + x1*x1 + x2*x2 + x3*x3;
    #pragma unroll
    for (int o = 16; o >= 1; o >>= 1) {
        sum += __shfl_xor_sync(0xffffffffu, sum, o);
        sq  += __shfl_xor_sync(0xffffffffu, sq,  o);
    }
    __shared__ float rs[8], rq[8];
    int w = tid >> 5, lane = tid & 31;
    if (lane == 0) { rs[w] = sum; rq[w] = sq; }
    __syncthreads();
    float ts = 0.f, tq = 0.f;
    #pragma unroll
    for (int i = 0; i < 8; i++) { ts += rs[i]; tq += rq[i]; }

    float mean = ts * (1.0f/1024.0f);
    float var  = (tq - 1024.0f * mean * mean) * (1.0f/1023.0f);  // ddof=1
    float stdv = sqrtf(var);

    float4 gv = *(const float4*)(gamma + tid*4);
    float4 bv = *(const float4*)(beta  + tid*4);
    float4 o4;
    o4.x = gv.x * (x0 - mean) / (stdv + 1e-6f + bv.x);
    o4.y = gv.y * (x1 - mean) / (stdv + 1e-6f + bv.y);
    o4.z = gv.z * (x2 - mean) / (stdv + 1e-6f + bv.z);
    o4.w = gv.w * (x3 - mean) / (stdv + 1e-6f + bv.w);
    *(float4*)(out + (size_t)row * Ee + tid*4) = o4;
}

// ---------------------------------------------------------------------------
// Launch.
// ---------------------------------------------------------------------------
extern "C" void kernel_launch(void* const* d_in, const int* in_sizes, int n_in,
                              void* d_out, int out_size)
{
    (void)in_sizes; (void)n_in; (void)out_size;
    const float* query = (const float*)d_in[0];
    const float* key   = (const float*)d_in[1];
    const float* value = (const float*)d_in[2];
    const float* resid = (const float*)d_in[3];
    const float* Wq = (const float*)d_in[4];
    const float* bq = (const float*)d_in[5];
    const float* Wk = (const float*)d_in[6];
    const float* bk = (const float*)d_in[7];
    const float* Wv = (const float*)d_in[8];
    const float* bv = (const float*)d_in[9];
    const float* gamma = (const float*)d_in[10];
    const float* beta  = (const float*)d_in[11];
    float* out = (float*)d_out;

    dim3 gproj(32, 8, 3);
    proj_kernel<<<gproj, 256>>>(query, key, value, Wq, Wk, Wv, bq, bk, bv);
    knorm_kernel<<<256, 256>>>();
    flash_kernel<<<dim3(32, 32, NSPLIT), 128>>>();
    ln_kernel<<<4096, 256>>>(resid, gamma, beta, out);
}

// round 12
// speedup vs baseline: 1.0081x; 1.0081x over previous
#include <cuda_runtime.h>
#include <cuda_bf16.h>
#include <cuda_fp16.h>

// Problem constants
#define Bb 2
#define Ss 2048
#define Ee 1024
#define Hh 16
#define Dd 64
#define SCALE (1.0f/32.0f)   // 1/sqrt(E)
#define NSPLIT 2             // flash key-splits

typedef __nv_bfloat16 bf;

// ---------------------------------------------------------------------------
// Scratch (device globals; allocation inside kernel_launch is forbidden)
// ---------------------------------------------------------------------------
__device__ bf     g_q  [(size_t)Bb*Hh*Ss*Dd];   // [b,h,s,d]
__device__ bf     g_kT [(size_t)Bb*Hh*Dd*Ss];   // [b,h,d,s] (transposed K)
__device__ bf     g_v  [(size_t)Bb*Hh*Ss*Dd];   // [b,h,s,d]
__device__ float  g_sk [(size_t)Bb*Hh*Ss];      // 0.5*SCALE*||k||^2 (from proj)
__device__ __half g_po [(size_t)NSPLIT*Bb*Hh*Ss*Dd];  // fp16 unnormalized partials
__device__ float  g_l  [(size_t)NSPLIT*Bb*Hh*Ss];     // partial softmax denoms

// ---------------------------------------------------------------------------
// Helpers
// ---------------------------------------------------------------------------
__device__ __forceinline__ unsigned s2u(const void* p) {
    return (unsigned)__cvta_generic_to_shared(p);
}
__device__ __forceinline__ unsigned f22bf(float x, float y) {
    __nv_bfloat162 h = __floats2bfloat162_rn(x, y);
    return *(unsigned*)&h;
}
__device__ __forceinline__ void mma_bf16(float* c, const unsigned* a, const unsigned* b) {
    asm volatile(
        "mma.sync.aligned.m16n8k16.row.col.f32.bf16.bf16.f32 "
        "{%0,%1,%2,%3}, {%4,%5,%6,%7}, {%8,%9}, {%0,%1,%2,%3};"
        : "+f"(c[0]), "+f"(c[1]), "+f"(c[2]), "+f"(c[3])
        : "r"(a[0]), "r"(a[1]), "r"(a[2]), "r"(a[3]), "r"(b[0]), "r"(b[1]));
}
__device__ __forceinline__ void ldmA(unsigned* a, unsigned saddr) {
    asm volatile("ldmatrix.sync.aligned.m8n8.x4.shared.b16 {%0,%1,%2,%3}, [%4];"
        : "=r"(a[0]), "=r"(a[1]), "=r"(a[2]), "=r"(a[3]) : "r"(saddr));
}
// B fragments for TWO adjacent n8 tiles (n16) in one x4.trans
__device__ __forceinline__ void ldmB4(unsigned* b, unsigned saddr) {
    asm volatile("ldmatrix.sync.aligned.m8n8.x4.trans.shared.b16 {%0,%1,%2,%3}, [%4];"
        : "=r"(b[0]), "=r"(b[1]), "=r"(b[2]), "=r"(b[3]) : "r"(saddr));
}
__device__ __forceinline__ void cp16(unsigned dst, const void* src) {
    asm volatile("cp.async.cg.shared.global [%0], [%1], 16;" :: "r"(dst), "l"(src));
}
#define CP_COMMIT() asm volatile("cp.async.commit_group;")
#define CP_WAIT0()  asm volatile("cp.async.wait_group 0;")

// ---------------------------------------------------------------------------
// Kernel 1: fused QKV projection, bf16 m16n8k16, fp32 accum (legacy mma —
// tcgen05 unavailable under this harness's sm_100 ptxas target).
// Block tile 128x128, K-chunk 32, double-buffered smem + register prefetch.
// z==1 additionally computes g_sk = 0.5*SCALE*||k||^2 in its epilogue
// (the 128-col n-tile covers exactly 2 full heads -> rows complete in-block).
// ---------------------------------------------------------------------------
__global__ __launch_bounds__(256, 2) void proj_kernel(
    const float* __restrict__ Xq, const float* __restrict__ Xk, const float* __restrict__ Xv,
    const float* __restrict__ Wq, const float* __restrict__ Wk, const float* __restrict__ Wv,
    const float* __restrict__ Bq, const float* __restrict__ Bk, const float* __restrict__ Bv)
{
    const int z = blockIdx.z;
    const float* X    = (z==0) ? Xq : ((z==1) ? Xk : Xv);
    const float* W    = (z==0) ? Wq : ((z==1) ? Wk : Wv);
    const float* bias = (z==0) ? Bq : ((z==1) ? Bk : Bv);

    __shared__ bf Xs[2][128][40];   // [buf][m][k], pad 8
    __shared__ bf Ws[2][32][136];   // [buf][k][n], pad 8

    const int tid  = threadIdx.x;
    const int wid  = tid >> 5, lane = tid & 31;
    const int g    = lane >> 2, qd = lane & 3;
    const int wm   = (wid & 1) * 64;
    const int wn   = (wid >> 1) * 32;
    const int m0   = blockIdx.x * 128;
    const int n0   = blockIdx.y * 128;

    const int arow_l = (lane & 7) + ((lane >> 3) & 1) * 8;
    const int acol_l = (lane >> 4) * 8;
    const int brow_l = (lane & 7) + ((lane >> 3) & 1) * 8;
    const int bcol_l = (lane >> 4) * 8;

    const int xr_r  = tid >> 3,  xr_c = (tid & 7) << 2;
    const int wr_k  = tid >> 5,  wr_c = (tid & 31) << 2;
    const int wn_h  = (n0 + wr_c) >> 6, wn_d = (n0 + wr_c) & 63;

    uint2 xr[4], wr[4];
    auto prefetch = [&](int k0) {
        #pragma unroll
        for (int u = 0; u < 4; u++) {
            float4 xv = *(const float4*)(X + (size_t)(m0 + xr_r + u*32) * Ee + k0 + xr_c);
            xr[u] = make_uint2(f22bf(xv.x, xv.y), f22bf(xv.z, xv.w));
            float4 wv = *(const float4*)(W + (size_t)wn_h * (Ee*Dd)
                                           + (size_t)(k0 + wr_k + u*8) * Dd + wn_d);
            wr[u] = make_uint2(f22bf(wv.x, wv.y), f22bf(wv.z, wv.w));
        }
    };

    float acc[4][4][4];
    #pragma unroll
    for (int mi = 0; mi < 4; mi++)
        #pragma unroll
        for (int nj = 0; nj < 4; nj++)
            #pragma unroll
            for (int r = 0; r < 4; r++) acc[mi][nj][r] = 0.f;

    prefetch(0);

    for (int k0 = 0; k0 < Ee; k0 += 32) {
        const int buf = (k0 >> 5) & 1;
        #pragma unroll
        for (int u = 0; u < 4; u++) {
            *(uint2*)&Xs[buf][xr_r + u*32][xr_c] = xr[u];
            *(uint2*)&Ws[buf][wr_k + u*8][wr_c] = wr[u];
        }
        __syncthreads();
        if (k0 + 32 < Ee) prefetch(k0 + 32);

        #pragma unroll
        for (int ks = 0; ks < 2; ks++) {
            unsigned a[4][4], b[2][4];
            #pragma unroll
            for (int mi = 0; mi < 4; mi++)
                ldmA(a[mi], s2u(&Xs[buf][wm + mi*16 + arow_l][ks*16 + acol_l]));
            #pragma unroll
            for (int p = 0; p < 2; p++)
                ldmB4(b[p], s2u(&Ws[buf][ks*16 + brow_l][wn + p*16 + bcol_l]));
            #pragma unroll
            for (int mi = 0; mi < 4; mi++)
                #pragma unroll
                for (int p = 0; p < 2; p++) {
                    mma_bf16(acc[mi][2*p    ], a[mi], &b[p][0]);
                    mma_bf16(acc[mi][2*p + 1], a[mi], &b[p][2]);
                }
        }
    }

    // Epilogue: +bias, convert/store; z==1 also accumulates row sum-squares
    float rowsq[4][2];
    #pragma unroll
    for (int mi = 0; mi < 4; mi++) { rowsq[mi][0] = 0.f; rowsq[mi][1] = 0.f; }

    #pragma unroll
    for (int mi = 0; mi < 4; mi++) {
        #pragma unroll
        for (int half = 0; half < 2; half++) {
            int m = m0 + wm + mi*16 + g + half*8;
            int bb = m >> 11, s = m & 2047;
            #pragma unroll
            for (int nj = 0; nj < 4; nj++) {
                int n = n0 + wn + nj*8 + 2*qd;
                int h = n >> 6, d = n & 63;
                float v0 = acc[mi][nj][half*2 + 0] + bias[h*Dd + d];
                float v1 = acc[mi][nj][half*2 + 1] + bias[h*Dd + d + 1];
                size_t bh = (size_t)bb * Hh + h;
                if (z == 1) {
                    rowsq[mi][half] = fmaf(v0, v0, rowsq[mi][half]);
                    rowsq[mi][half] = fmaf(v1, v1, rowsq[mi][half]);
                    g_kT[(bh*Dd + d    )*Ss + s] = __float2bfloat16_rn(v0);
                    g_kT[(bh*Dd + d + 1)*Ss + s] = __float2bfloat16_rn(v1);
                } else {
                    bf* out = (z == 0) ? g_q : g_v;
                    *(unsigned*)&out[(bh*Ss + s)*Dd + d] = f22bf(v0, v1);
                }
            }
        }
    }

    if (z == 1) {
        // reduce ||k||^2 per (row, head) and store g_sk
        float* sksum = (float*)Xs;    // [128][4]; Xs is dead after the sync below
        __syncthreads();              // all warps done reading Xs/Ws
        #pragma unroll
        for (int mi = 0; mi < 4; mi++)
            #pragma unroll
            for (int half = 0; half < 2; half++) {
                float v = rowsq[mi][half];
                v += __shfl_xor_sync(0xffffffffu, v, 1);   // quad lanes share the row
                v += __shfl_xor_sync(0xffffffffu, v, 2);
                if (qd == 0)
                    sksum[(wm + mi*16 + g + half*8)*4 + (wid >> 1)] = v;
            }
        __syncthreads();
        // row covers cols: sksum[row][0..1] = head n0>>6, [2..3] = head (n0>>6)+1
        {
            int row = tid >> 1, hh = tid & 1;   // 256 threads -> 128 rows x 2 heads
            int m = m0 + row;
            int bb = m >> 11, s = m & 2047;
            float v = sksum[row*4 + 2*hh] + sksum[row*4 + 2*hh + 1];
            int h = (n0 >> 6) + hh;
            g_sk[((size_t)bb*Hh + h)*Ss + s] = 0.5f * SCALE * v;
        }
    }
}

// ---------------------------------------------------------------------------
// Kernel 2: flash attention, bf16 m16n8k16, fixed-max softmax, SPLIT-K (2).
// BQ=64, 4 warps; each block covers 1024 keys.  Writes fp16 UNNORMALIZED
// partial output + fp32 partial l; combine fused into ln_kernel.
// ---------------------------------------------------------------------------
__global__ __launch_bounds__(128) void flash_kernel()
{
    __shared__ __align__(16) unsigned char smbuf[40960];
    bf* Ks[2] = { (bf*)smbuf,            (bf*)(smbuf +  9216) };   // [64][72]
    bf* Vs[2] = { (bf*)(smbuf + 18432),  (bf*)(smbuf + 27648) };   // [64][72]
    float* sks = (float*)(smbuf + 36864);                          // [1024]

    const int bh = blockIdx.y;
    const int q0 = blockIdx.x * 64;
    const int ksp = blockIdx.z;               // 0..NSPLIT-1
    const int kbase = ksp * (Ss / NSPLIT);
    const int tid = threadIdx.x;
    const int wid = tid >> 5, lane = tid & 31;
    const int g = lane >> 2, qd = lane & 3;

    const bf* Qg   = g_q  + ((size_t)bh * Ss + q0) * Dd;
    const bf* KTg  = g_kT + (size_t)bh * Dd * Ss;
    const bf* Vg   = g_v  + (size_t)bh * Ss * Dd;
    const float* skg = g_sk + (size_t)bh * Ss + kbase;

    const int arow_l = (lane & 7) + ((lane >> 3) & 1) * 8;
    const int acol_l = (lane >> 4) * 8;
    const int brow_l = (lane & 7) + ((lane >> 3) & 1) * 8;
    const int bcol_l = (lane >> 4) * 8;
    const int wrow = wid * 16;
    const int crow = wrow + g;

    const int ld_r  = tid >> 3;
    const int ld_c8 = (tid & 7) << 3;

    // ---- Prologue: Q -> staging (Ks[0]) -> A regs; this split's sk row ----
    {
        bf* Qst = Ks[0];
        #pragma unroll
        for (int u = 0; u < 4; u++)
            *(uint4*)&Qst[(ld_r + u*16)*72 + ld_c8] =
                *(const uint4*)(Qg + (size_t)(ld_r + u*16) * Dd + ld_c8);
        #pragma unroll
        for (int u = 0; u < 2; u++) {
            int idx = u * 128 + tid;
            *(float4*)&sks[idx*4] = *(const float4*)(skg + idx*4);
        }
        __syncthreads();
    }
    unsigned qa[4][4];
    #pragma unroll
    for (int t = 0; t < 4; t++)
        ldmA(qa[t], s2u(&Ks[0][(wrow + arow_l)*72 + t*16 + acol_l]));

    // row constants: 0.5*SCALE*||q||^2 for rows crow and crow+8
    float sq0 = 0.f, sq1 = 0.f;
    {
        const bf* r0 = &Ks[0][crow*72];
        const bf* r1 = &Ks[0][(crow+8)*72];
        #pragma unroll
        for (int d = 0; d < Dd; d++) {
            float v0 = __bfloat162float(r0[d]);
            float v1 = __bfloat162float(r1[d]);
            sq0 = fmaf(v0, v0, sq0);
            sq1 = fmaf(v1, v1, sq1);
        }
        sq0 *= 0.5f * SCALE;
        sq1 *= 0.5f * SCALE;
    }
    __syncthreads();   // Q staging dead; cp.async may overwrite

    auto issue_loads = [&](int buf, int k0) {
        #pragma unroll
        for (int u = 0; u < 4; u++) {
            int r = ld_r + u*16;
            cp16(s2u(&Ks[buf][r*72 + ld_c8]), KTg + (size_t)r * Ss + k0 + ld_c8);
            cp16(s2u(&Vs[buf][r*72 + ld_c8]), Vg  + (size_t)(k0 + r) * Dd + ld_c8);
        }
        CP_COMMIT();
    };
    issue_loads(0, kbase);

    float l0 = 0.f, l1 = 0.f;
    float oacc[8][4];
    #pragma unroll
    for (int j = 0; j < 8; j++)
        #pragma unroll
        for (int r = 0; r < 4; r++) oacc[j][r] = 0.f;

    const int NIT = (Ss / NSPLIT) / 64;   // 16
    for (int it = 0; it < NIT; it++) {
        const int k0 = kbase + it * 64;
        const int buf = it & 1;
        CP_WAIT0();
        __syncthreads();
        if (it + 1 < NIT) issue_loads(buf ^ 1, k0 + 64);

        // ---- scores: Q(reg) x K^T[d][key] ----
        float sc[8][4];
        #pragma unroll
        for (int j = 0; j < 8; j++)
            #pragma unroll
            for (int r = 0; r < 4; r++) sc[j][r] = 0.f;

        #pragma unroll
        for (int t = 0; t < 4; t++) {
            #pragma unroll
            for (int p = 0; p < 4; p++) {
                unsigned b[4];
                ldmB4(b, s2u(&Ks[buf][(t*16 + brow_l)*72 + p*16 + bcol_l]));
                mma_bf16(sc[2*p    ], qa[t], &b[0]);
                mma_bf16(sc[2*p + 1], qa[t], &b[2]);
            }
        }

        // ---- exact softmax, fixed max 0: p = exp(qk*SCALE - sk - sq) ----
        #pragma unroll
        for (int j = 0; j < 8; j++) {
            #pragma unroll
            for (int c = 0; c < 2; c++) {
                float skc = sks[it*64 + j*8 + 2*qd + c];
                float p0 = __expf(fmaf(sc[j][c],   SCALE, -skc) - sq0);
                float p1 = __expf(fmaf(sc[j][2+c], SCALE, -skc) - sq1);
                sc[j][c]   = p0; l0 += p0;
                sc[j][2+c] = p1; l1 += p1;
            }
        }

        // ---- PV: P straight from registers (C-frag == A-frag layout) ----
        #pragma unroll
        for (int t = 0; t < 4; t++) {
            unsigned a[4];
            a[0] = f22bf(sc[2*t  ][0], sc[2*t  ][1]);
            a[1] = f22bf(sc[2*t  ][2], sc[2*t  ][3]);
            a[2] = f22bf(sc[2*t+1][0], sc[2*t+1][1]);
            a[3] = f22bf(sc[2*t+1][2], sc[2*t+1][3]);
            #pragma unroll
            for (int p = 0; p < 4; p++) {
                unsigned b[4];
                ldmB4(b, s2u(&Vs[buf][(t*16 + brow_l)*72 + p*16 + bcol_l]));
                mma_bf16(oacc[2*p    ], a, &b[0]);
                mma_bf16(oacc[2*p + 1], a, &b[2]);
            }
        }
    }

    // reduce l across the 4 qd lanes once
    l0 += __shfl_xor_sync(0xffffffffu, l0, 1);
    l0 += __shfl_xor_sync(0xffffffffu, l0, 2);
    l1 += __shfl_xor_sync(0xffffffffu, l1, 1);
    l1 += __shfl_xor_sync(0xffffffffu, l1, 2);

    // Epilogue: fp16 UNNORMALIZED partial out + fp32 l (combined in ln_kernel)
    const int s0 = q0 + crow, s1 = s0 + 8;
    __half* po = g_po + ((size_t)ksp * (Bb*Hh) + bh) * (Ss * Dd);
    #pragma unroll
    for (int j = 0; j < 8; j++) {
        int col = j*8 + 2*qd;
        *(__half2*)&po[(size_t)s0 * Dd + col] = __floats2half2_rn(oacc[j][0], oacc[j][1]);
        *(__half2*)&po[(size_t)s1 * Dd + col] = __floats2half2_rn(oacc[j][2], oacc[j][3]);
    }
    if (qd == 0) {
        float* pl = g_l + ((size_t)ksp * (Bb*Hh) + bh) * Ss;
        pl[s0] = l0;
        pl[s1] = l1;
    }
}

// ---------------------------------------------------------------------------
// Kernel 3: split-combine + residual add + custom LayerNorm.
// x = (po0+po1)/(l0+l1) + resid;  out = scale*(x-mean)/(std_ddof1+eps+shift)
// ---------------------------------------------------------------------------
__global__ __launch_bounds__(256) void ln_kernel(
    const float* __restrict__ resid, const float* __restrict__ gamma,
    const float* __restrict__ beta, float* __restrict__ out)
{
    const int row = blockIdx.x;            // b*2048 + s
    const int b = row >> 11, s = row & 2047;
    const int tid = threadIdx.x;
    const int h = tid >> 4;
    const int dv4 = (tid & 15) << 2;
    const size_t bh = (size_t)b * Hh + h;

    const __half* po0 = g_po + (bh                ) * (Ss * Dd) + (size_t)s * Dd + dv4;
    const __half* po1 = g_po + ((size_t)Bb*Hh + bh) * (Ss * Dd) + (size_t)s * Dd + dv4;
    float linv = 1.0f / (g_l[bh * Ss + s] + g_l[((size_t)Bb*Hh + bh) * Ss + s]);

    float2 a00 = __half22float2(*(const __half2*)(po0    ));
    float2 a01 = __half22float2(*(const __half2*)(po0 + 2));
    float2 a10 = __half22float2(*(const __half2*)(po1    ));
    float2 a11 = __half22float2(*(const __half2*)(po1 + 2));
    float4 r  = *(const float4*)(resid + (size_t)row * Ee + tid*4);
    float x0 = (a00.x + a10.x) * linv + r.x;
    float x1 = (a00.y + a10.y) * linv + r.y;
    float x2 = (a01.x + a11.x) * linv + r.z;
    float x3 = (a01.y + a11.y) * linv + r.w;

    float sum = x0 + x1 + x2 + x3;
    float sq  = x0*x0 + x1*x1 + x2*x2 + x3*x3;
    #pragma unroll
    for (int o = 16; o >= 1; o >>= 1) {
        sum += __shfl_xor_sync(0xffffffffu, sum, o);
        sq  += __shfl_xor_sync(0xffffffffu, sq,  o);
    }
    __shared__ float rs[8], rq[8];
    int w = tid >> 5, lane = tid & 31;
    if (lane == 0) { rs[w] = sum; rq[w] = sq; }
    __syncthreads();
    float ts = 0.f, tq = 0.f;
    #pragma unroll
    for (int i = 0; i < 8; i++) { ts += rs[i]; tq += rq[i]; }

    float mean = ts * (1.0f/1024.0f);
    float var  = (tq - 1024.0f * mean * mean) * (1.0f/1023.0f);  // ddof=1
    float stdv = sqrtf(var);

    float4 gv = *(const float4*)(gamma + tid*4);
    float4 bv = *(const float4*)(beta  + tid*4);
    float4 o4;
    o4.x = gv.x * (x0 - mean) / (stdv + 1e-6f + bv.x);
    o4.y = gv.y * (x1 - mean) / (stdv + 1e-6f + bv.y);
    o4.z = gv.z * (x2 - mean) / (stdv + 1e-6f + bv.z);
    o4.w = gv.w * (x3 - mean) / (stdv + 1e-6f + bv.w);
    *(float4*)(out + (size_t)row * Ee + tid*4) = o4;
}

// ---------------------------------------------------------------------------
// Launch.
// ---------------------------------------------------------------------------
extern "C" void kernel_launch(void* const* d_in, const int* in_sizes, int n_in,
                              void* d_out, int out_size)
{
    (void)in_sizes; (void)n_in; (void)out_size;
    const float* query = (const float*)d_in[0];
    const float* key   = (const float*)d_in[1];
    const float* value = (const float*)d_in[2];
    const float* resid = (const float*)d_in[3];
    const float* Wq = (const float*)d_in[4];
    const float* bq = (const float*)d_in[5];
    const float* Wk = (const float*)d_in[6];
    const float* bk = (const float*)d_in[7];
    const float* Wv = (const float*)d_in[8];
    const float* bv = (const float*)d_in[9];
    const float* gamma = (const float*)d_in[10];
    const float* beta  = (const float*)d_in[11];
    float* out = (float*)d_out;

    dim3 gproj(32, 8, 3);
    proj_kernel<<<gproj, 256>>>(query, key, value, Wq, Wk, Wv, bq, bk, bv);
    flash_kernel<<<dim3(32, 32, NSPLIT), 128>>>();
    ln_kernel<<<4096, 256>>>(resid, gamma, beta, out);
}

// round 13
// speedup vs baseline: 1.0571x; 1.0486x over previous
#include <cuda_runtime.h>
#include <cuda_bf16.h>
#include <cuda_fp16.h>

// Problem constants
#define Bb 2
#define Ss 2048
#define Ee 1024
#define Hh 16
#define Dd 64
#define SCALE (1.0f/32.0f)   // 1/sqrt(E)
#define NSPLIT 2             // flash key-splits

typedef __nv_bfloat16 bf;

// X region: 3 tensors of Bb*Ss*Ee ; W region: 3 tensors of Hh*Ee*Dd
#define NXE ((size_t)Bb*Ss*Ee)          // 4194304
#define NWE ((size_t)Hh*Ee*Dd)          // 1048576

// ---------------------------------------------------------------------------
// Scratch (device globals; allocation inside kernel_launch is forbidden)
// ---------------------------------------------------------------------------
__device__ bf     g_xw [3*NXE + 3*NWE];         // bf16 pre-converted X then W
__device__ bf     g_q  [(size_t)Bb*Hh*Ss*Dd];   // [b,h,s,d]
__device__ bf     g_kT [(size_t)Bb*Hh*Dd*Ss];   // [b,h,d,s] (transposed K)
__device__ bf     g_v  [(size_t)Bb*Hh*Ss*Dd];   // [b,h,s,d]
__device__ float  g_sk [(size_t)Bb*Hh*Ss];      // 0.5*SCALE*||k||^2 (from proj)
__device__ __half g_po [(size_t)NSPLIT*Bb*Hh*Ss*Dd];  // fp16 unnormalized partials
__device__ float  g_l  [(size_t)NSPLIT*Bb*Hh*Ss];     // partial softmax denoms

// ---------------------------------------------------------------------------
// Helpers
// ---------------------------------------------------------------------------
__device__ __forceinline__ unsigned s2u(const void* p) {
    return (unsigned)__cvta_generic_to_shared(p);
}
__device__ __forceinline__ unsigned f22bf(float x, float y) {
    __nv_bfloat162 h = __floats2bfloat162_rn(x, y);
    return *(unsigned*)&h;
}
__device__ __forceinline__ void mma_bf16(float* c, const unsigned* a, const unsigned* b) {
    asm volatile(
        "mma.sync.aligned.m16n8k16.row.col.f32.bf16.bf16.f32 "
        "{%0,%1,%2,%3}, {%4,%5,%6,%7}, {%8,%9}, {%0,%1,%2,%3};"
        : "+f"(c[0]), "+f"(c[1]), "+f"(c[2]), "+f"(c[3])
        : "r"(a[0]), "r"(a[1]), "r"(a[2]), "r"(a[3]), "r"(b[0]), "r"(b[1]));
}
__device__ __forceinline__ void ldmA(unsigned* a, unsigned saddr) {
    asm volatile("ldmatrix.sync.aligned.m8n8.x4.shared.b16 {%0,%1,%2,%3}, [%4];"
        : "=r"(a[0]), "=r"(a[1]), "=r"(a[2]), "=r"(a[3]) : "r"(saddr));
}
__device__ __forceinline__ void ldmB4(unsigned* b, unsigned saddr) {
    asm volatile("ldmatrix.sync.aligned.m8n8.x4.trans.shared.b16 {%0,%1,%2,%3}, [%4];"
        : "=r"(b[0]), "=r"(b[1]), "=r"(b[2]), "=r"(b[3]) : "r"(saddr));
}
__device__ __forceinline__ void cp16(unsigned dst, const void* src) {
    asm volatile("cp.async.cg.shared.global [%0], [%1], 16;" :: "r"(dst), "l"(src));
}
#define CP_COMMIT()  asm volatile("cp.async.commit_group;")
#define CP_WAIT0()   asm volatile("cp.async.wait_group 0;")
#define CP_WAIT2()   asm volatile("cp.async.wait_group 2;")

// ---------------------------------------------------------------------------
// Kernel 0: fp32 -> bf16 pre-conversion of X (q,k,v inputs) and W (wq,wk,wv).
// ---------------------------------------------------------------------------
__global__ __launch_bounds__(256) void cvt_kernel(
    const float* __restrict__ xq, const float* __restrict__ xk, const float* __restrict__ xv,
    const float* __restrict__ wq, const float* __restrict__ wk, const float* __restrict__ wv)
{
    const size_t NX4 = NXE / 4;          // float4 count per X tensor
    const size_t NW4 = NWE / 4;
    size_t i4 = (size_t)blockIdx.x * 256 + threadIdx.x;
    const float* src;
    bf* dst;
    size_t off;
    if (i4 < 3 * NX4) {
        int z = (int)(i4 / NX4);
        off = (i4 % NX4) * 4;
        src = (z == 0) ? xq : ((z == 1) ? xk : xv);
        dst = g_xw + (size_t)z * NXE;
    } else {
        size_t j4 = i4 - 3 * NX4;
        if (j4 >= 3 * NW4) return;
        int z = (int)(j4 / NW4);
        off = (j4 % NW4) * 4;
        src = (z == 0) ? wq : ((z == 1) ? wk : wv);
        dst = g_xw + 3 * NXE + (size_t)z * NWE;
    }
    float4 v = *(const float4*)(src + off);
    *(uint2*)(dst + off) = make_uint2(f22bf(v.x, v.y), f22bf(v.z, v.w));
}

// ---------------------------------------------------------------------------
// Kernel 1: fused QKV projection, bf16 m16n8k16, cp.async 4-STAGE pipeline
// (inputs pre-converted to bf16 -> no register prefetch, no raw-LDG stalls).
// Block tile 128x128, K-chunk 32.  z==1 also computes g_sk in its epilogue.
// Dynamic smem: 4 stages x (Xs[128][40] + Ws[32][136]) = 75776 B.
// ---------------------------------------------------------------------------
#define XS_BYTES (128*40*2)      // 10240
#define WS_BYTES (32*136*2)      // 8704
#define STAGE_BYTES (XS_BYTES + WS_BYTES)   // 18944
#define NCHUNK (Ee/32)           // 32

__global__ __launch_bounds__(256, 2) void proj_kernel(
    const float* __restrict__ Bq, const float* __restrict__ Bk, const float* __restrict__ Bv)
{
    extern __shared__ __align__(16) unsigned char dynsm[];

    const int z = blockIdx.z;
    const bf* Xg = g_xw + (size_t)z * NXE;
    const bf* Wg = g_xw + 3 * NXE + (size_t)z * NWE;
    const float* bias = (z==0) ? Bq : ((z==1) ? Bk : Bv);

    const int tid  = threadIdx.x;
    const int wid  = tid >> 5, lane = tid & 31;
    const int g    = lane >> 2, qd = lane & 3;
    const int wm   = (wid & 1) * 64;
    const int wn   = (wid >> 1) * 32;
    const int m0   = blockIdx.x * 128;
    const int n0   = blockIdx.y * 128;

    const int arow_l = (lane & 7) + ((lane >> 3) & 1) * 8;
    const int acol_l = (lane >> 4) * 8;
    const int brow_l = (lane & 7) + ((lane >> 3) & 1) * 8;
    const int bcol_l = (lane >> 4) * 8;

    // cp.async mapping (2 chunks each for X and W per thread per stage)
    //   X: idx in [0,512): r = idx>>2 (0..127), c = (idx&3)*8 bf16 cols
    //   W: idx in [0,512): kk = idx>>4 (0..31), c = (idx&15)*8 bf16 cols
    auto issue_loads = [&](int stage, int k0) {
        unsigned char* Xs = dynsm + stage * STAGE_BYTES;
        unsigned char* Ws = Xs + XS_BYTES;
        #pragma unroll
        for (int u = 0; u < 2; u++) {
            int idx = u * 256 + tid;
            int r = idx >> 2, c = (idx & 3) * 8;
            cp16(s2u(Xs + r*80 + c*2), Xg + (size_t)(m0 + r) * Ee + k0 + c);
            int kk = idx >> 4, cw = (idx & 15) * 8;
            int n = n0 + cw, h = n >> 6, d = n & 63;
            cp16(s2u(Ws + kk*272 + cw*2),
                 Wg + (size_t)h * (Ee*Dd) + (size_t)(k0 + kk) * Dd + d);
        }
        CP_COMMIT();
    };

    float acc[4][4][4];
    #pragma unroll
    for (int mi = 0; mi < 4; mi++)
        #pragma unroll
        for (int nj = 0; nj < 4; nj++)
            #pragma unroll
            for (int r = 0; r < 4; r++) acc[mi][nj][r] = 0.f;

    // prologue: stages 0,1,2 in flight
    issue_loads(0, 0);
    issue_loads(1, 32);
    issue_loads(2, 64);

    for (int it = 0; it < NCHUNK; it++) {
        const int stage = it & 3;
        CP_WAIT2();            // group for stage `it` complete (uniform group count)
        __syncthreads();       // also: all warps done reading stage (it-1)&3
        // keep group count uniform: always commit, load only if real
        if (it + 3 < NCHUNK) {
            issue_loads((it + 3) & 3, (it + 3) * 32);
        } else {
            CP_COMMIT();       // empty group
        }

        unsigned char* Xs = dynsm + stage * STAGE_BYTES;
        unsigned char* Ws = Xs + XS_BYTES;
        #pragma unroll
        for (int ks = 0; ks < 2; ks++) {
            unsigned a[4][4], b[2][4];
            #pragma unroll
            for (int mi = 0; mi < 4; mi++)
                ldmA(a[mi], s2u(Xs + (wm + mi*16 + arow_l)*80 + (ks*16 + acol_l)*2));
            #pragma unroll
            for (int p = 0; p < 2; p++)
                ldmB4(b[p], s2u(Ws + (ks*16 + brow_l)*272 + (wn + p*16 + bcol_l)*2));
            #pragma unroll
            for (int mi = 0; mi < 4; mi++)
                #pragma unroll
                for (int p = 0; p < 2; p++) {
                    mma_bf16(acc[mi][2*p    ], a[mi], &b[p][0]);
                    mma_bf16(acc[mi][2*p + 1], a[mi], &b[p][2]);
                }
        }
    }

    // Epilogue: +bias, convert/store; z==1 also accumulates row sum-squares
    float rowsq[4][2];
    #pragma unroll
    for (int mi = 0; mi < 4; mi++) { rowsq[mi][0] = 0.f; rowsq[mi][1] = 0.f; }

    #pragma unroll
    for (int mi = 0; mi < 4; mi++) {
        #pragma unroll
        for (int half = 0; half < 2; half++) {
            int m = m0 + wm + mi*16 + g + half*8;
            int bb = m >> 11, s = m & 2047;
            #pragma unroll
            for (int nj = 0; nj < 4; nj++) {
                int n = n0 + wn + nj*8 + 2*qd;
                int h = n >> 6, d = n & 63;
                float v0 = acc[mi][nj][half*2 + 0] + bias[h*Dd + d];
                float v1 = acc[mi][nj][half*2 + 1] + bias[h*Dd + d + 1];
                size_t bh = (size_t)bb * Hh + h;
                if (z == 1) {
                    rowsq[mi][half] = fmaf(v0, v0, rowsq[mi][half]);
                    rowsq[mi][half] = fmaf(v1, v1, rowsq[mi][half]);
                    g_kT[(bh*Dd + d    )*Ss + s] = __float2bfloat16_rn(v0);
                    g_kT[(bh*Dd + d + 1)*Ss + s] = __float2bfloat16_rn(v1);
                } else {
                    bf* out = (z == 0) ? g_q : g_v;
                    *(unsigned*)&out[(bh*Ss + s)*Dd + d] = f22bf(v0, v1);
                }
            }
        }
    }

    if (z == 1) {
        // reduce ||k||^2 per (row, head) and store g_sk
        float* sksum = (float*)dynsm;   // [128][4]; tiles dead after the sync below
        CP_WAIT0();                     // drain any pending (empty) groups
        __syncthreads();                // all warps done with smem tiles
        #pragma unroll
        for (int mi = 0; mi < 4; mi++)
            #pragma unroll
            for (int half = 0; half < 2; half++) {
                float v = rowsq[mi][half];
                v += __shfl_xor_sync(0xffffffffu, v, 1);   // quad lanes share the row
                v += __shfl_xor_sync(0xffffffffu, v, 2);
                if (qd == 0)
                    sksum[(wm + mi*16 + g + half*8)*4 + (wid >> 1)] = v;
            }
        __syncthreads();
        {
            int row = tid >> 1, hh = tid & 1;   // 256 threads -> 128 rows x 2 heads
            int m = m0 + row;
            int bb = m >> 11, s = m & 2047;
            float v = sksum[row*4 + 2*hh] + sksum[row*4 + 2*hh + 1];
            int h = (n0 >> 6) + hh;
            g_sk[((size_t)bb*Hh + h)*Ss + s] = 0.5f * SCALE * v;
        }
    }
}

// ---------------------------------------------------------------------------
// Kernel 2: flash attention, bf16 m16n8k16, fixed-max softmax, SPLIT-K (2).
// BQ=64, 4 warps; each block covers 1024 keys.  Writes fp16 UNNORMALIZED
// partial output + fp32 partial l; combine fused into ln_kernel.
// ---------------------------------------------------------------------------
__global__ __launch_bounds__(128) void flash_kernel()
{
    __shared__ __align__(16) unsigned char smbuf[40960];
    bf* Ks[2] = { (bf*)smbuf,            (bf*)(smbuf +  9216) };   // [64][72]
    bf* Vs[2] = { (bf*)(smbuf + 18432),  (bf*)(smbuf + 27648) };   // [64][72]
    float* sks = (float*)(smbuf + 36864);                          // [1024]

    const int bh = blockIdx.y;
    const int q0 = blockIdx.x * 64;
    const int ksp = blockIdx.z;               // 0..NSPLIT-1
    const int kbase = ksp * (Ss / NSPLIT);
    const int tid = threadIdx.x;
    const int wid = tid >> 5, lane = tid & 31;
    const int g = lane >> 2, qd = lane & 3;

    const bf* Qg   = g_q  + ((size_t)bh * Ss + q0) * Dd;
    const bf* KTg  = g_kT + (size_t)bh * Dd * Ss;
    const bf* Vg   = g_v  + (size_t)bh * Ss * Dd;
    const float* skg = g_sk + (size_t)bh * Ss + kbase;

    const int arow_l = (lane & 7) + ((lane >> 3) & 1) * 8;
    const int acol_l = (lane >> 4) * 8;
    const int brow_l = (lane & 7) + ((lane >> 3) & 1) * 8;
    const int bcol_l = (lane >> 4) * 8;
    const int wrow = wid * 16;
    const int crow = wrow + g;

    const int ld_r  = tid >> 3;
    const int ld_c8 = (tid & 7) << 3;

    // ---- Prologue: Q -> staging (Ks[0]) -> A regs; this split's sk row ----
    {
        bf* Qst = Ks[0];
        #pragma unroll
        for (int u = 0; u < 4; u++)
            *(uint4*)&Qst[(ld_r + u*16)*72 + ld_c8] =
                *(const uint4*)(Qg + (size_t)(ld_r + u*16) * Dd + ld_c8);
        #pragma unroll
        for (int u = 0; u < 2; u++) {
            int idx = u * 128 + tid;
            *(float4*)&sks[idx*4] = *(const float4*)(skg + idx*4);
        }
        __syncthreads();
    }
    unsigned qa[4][4];
    #pragma unroll
    for (int t = 0; t < 4; t++)
        ldmA(qa[t], s2u(&Ks[0][(wrow + arow_l)*72 + t*16 + acol_l]));

    // row constants: 0.5*SCALE*||q||^2 for rows crow and crow+8
    float sq0 = 0.f, sq1 = 0.f;
    {
        const bf* r0 = &Ks[0][crow*72];
        const bf* r1 = &Ks[0][(crow+8)*72];
        #pragma unroll
        for (int d = 0; d < Dd; d++) {
            float v0 = __bfloat162float(r0[d]);
            float v1 = __bfloat162float(r1[d]);
            sq0 = fmaf(v0, v0, sq0);
            sq1 = fmaf(v1, v1, sq1);
        }
        sq0 *= 0.5f * SCALE;
        sq1 *= 0.5f * SCALE;
    }
    __syncthreads();   // Q staging dead; cp.async may overwrite

    auto issue_loads = [&](int buf, int k0) {
        #pragma unroll
        for (int u = 0; u < 4; u++) {
            int r = ld_r + u*16;
            cp16(s2u(&Ks[buf][r*72 + ld_c8]), KTg + (size_t)r * Ss + k0 + ld_c8);
            cp16(s2u(&Vs[buf][r*72 + ld_c8]), Vg  + (size_t)(k0 + r) * Dd + ld_c8);
        }
        CP_COMMIT();
    };
    issue_loads(0, kbase);

    float l0 = 0.f, l1 = 0.f;
    float oacc[8][4];
    #pragma unroll
    for (int j = 0; j < 8; j++)
        #pragma unroll
        for (int r = 0; r < 4; r++) oacc[j][r] = 0.f;

    const int NIT = (Ss / NSPLIT) / 64;   // 16
    for (int it = 0; it < NIT; it++) {
        const int k0 = kbase + it * 64;
        const int buf = it & 1;
        CP_WAIT0();
        __syncthreads();
        if (it + 1 < NIT) issue_loads(buf ^ 1, k0 + 64);

        // ---- scores: Q(reg) x K^T[d][key] ----
        float sc[8][4];
        #pragma unroll
        for (int j = 0; j < 8; j++)
            #pragma unroll
            for (int r = 0; r < 4; r++) sc[j][r] = 0.f;

        #pragma unroll
        for (int t = 0; t < 4; t++) {
            #pragma unroll
            for (int p = 0; p < 4; p++) {
                unsigned b[4];
                ldmB4(b, s2u(&Ks[buf][(t*16 + brow_l)*72 + p*16 + bcol_l]));
                mma_bf16(sc[2*p    ], qa[t], &b[0]);
                mma_bf16(sc[2*p + 1], qa[t], &b[2]);
            }
        }

        // ---- exact softmax, fixed max 0: p = exp(qk*SCALE - sk - sq) ----
        #pragma unroll
        for (int j = 0; j < 8; j++) {
            #pragma unroll
            for (int c = 0; c < 2; c++) {
                float skc = sks[it*64 + j*8 + 2*qd + c];
                float p0 = __expf(fmaf(sc[j][c],   SCALE, -skc) - sq0);
                float p1 = __expf(fmaf(sc[j][2+c], SCALE, -skc) - sq1);
                sc[j][c]   = p0; l0 += p0;
                sc[j][2+c] = p1; l1 += p1;
            }
        }

        // ---- PV: P straight from registers (C-frag == A-frag layout) ----
        #pragma unroll
        for (int t = 0; t < 4; t++) {
            unsigned a[4];
            a[0] = f22bf(sc[2*t  ][0], sc[2*t  ][1]);
            a[1] = f22bf(sc[2*t  ][2], sc[2*t  ][3]);
            a[2] = f22bf(sc[2*t+1][0], sc[2*t+1][1]);
            a[3] = f22bf(sc[2*t+1][2], sc[2*t+1][3]);
            #pragma unroll
            for (int p = 0; p < 4; p++) {
                unsigned b[4];
                ldmB4(b, s2u(&Vs[buf][(t*16 + brow_l)*72 + p*16 + bcol_l]));
                mma_bf16(oacc[2*p    ], a, &b[0]);
                mma_bf16(oacc[2*p + 1], a, &b[2]);
            }
        }
    }

    // reduce l across the 4 qd lanes once
    l0 += __shfl_xor_sync(0xffffffffu, l0, 1);
    l0 += __shfl_xor_sync(0xffffffffu, l0, 2);
    l1 += __shfl_xor_sync(0xffffffffu, l1, 1);
    l1 += __shfl_xor_sync(0xffffffffu, l1, 2);

    // Epilogue: fp16 UNNORMALIZED partial out + fp32 l (combined in ln_kernel)
    const int s0 = q0 + crow, s1 = s0 + 8;
    __half* po = g_po + ((size_t)ksp * (Bb*Hh) + bh) * (Ss * Dd);
    #pragma unroll
    for (int j = 0; j < 8; j++) {
        int col = j*8 + 2*qd;
        *(__half2*)&po[(size_t)s0 * Dd + col] = __floats2half2_rn(oacc[j][0], oacc[j][1]);
        *(__half2*)&po[(size_t)s1 * Dd + col] = __floats2half2_rn(oacc[j][2], oacc[j][3]);
    }
    if (qd == 0) {
        float* pl = g_l + ((size_t)ksp * (Bb*Hh) + bh) * Ss;
        pl[s0] = l0;
        pl[s1] = l1;
    }
}

// ---------------------------------------------------------------------------
// Kernel 3: split-combine + residual add + custom LayerNorm.
// ---------------------------------------------------------------------------
__global__ __launch_bounds__(256) void ln_kernel(
    const float* __restrict__ resid, const float* __restrict__ gamma,
    const float* __restrict__ beta, float* __restrict__ out)
{
    const int row = blockIdx.x;            // b*2048 + s
    const int b = row >> 11, s = row & 2047;
    const int tid = threadIdx.x;
    const int h = tid >> 4;
    const int dv4 = (tid & 15) << 2;
    const size_t bh = (size_t)b * Hh + h;

    const __half* po0 = g_po + (bh                ) * (Ss * Dd) + (size_t)s * Dd + dv4;
    const __half* po1 = g_po + ((size_t)Bb*Hh + bh) * (Ss * Dd) + (size_t)s * Dd + dv4;
    float linv = 1.0f / (g_l[bh * Ss + s] + g_l[((size_t)Bb*Hh + bh) * Ss + s]);

    float2 a00 = __half22float2(*(const __half2*)(po0    ));
    float2 a01 = __half22float2(*(const __half2*)(po0 + 2));
    float2 a10 = __half22float2(*(const __half2*)(po1    ));
    float2 a11 = __half22float2(*(const __half2*)(po1 + 2));
    float4 r  = *(const float4*)(resid + (size_t)row * Ee + tid*4);
    float x0 = (a00.x + a10.x) * linv + r.x;
    float x1 = (a00.y + a10.y) * linv + r.y;
    float x2 = (a01.x + a11.x) * linv + r.z;
    float x3 = (a01.y + a11.y) * linv + r.w;

    float sum = x0 + x1 + x2 + x3;
    float sq  = x0*x0 + x1*x1 + x2*x2 + x3*x3;
    #pragma unroll
    for (int o = 16; o >= 1; o >>= 1) {
        sum += __shfl_xor_sync(0xffffffffu, sum, o);
        sq  += __shfl_xor_sync(0xffffffffu, sq,  o);
    }
    __shared__ float rs[8], rq[8];
    int w = tid >> 5, lane = tid & 31;
    if (lane == 0) { rs[w] = sum; rq[w] = sq; }
    __syncthreads();
    float ts = 0.f, tq = 0.f;
    #pragma unroll
    for (int i = 0; i < 8; i++) { ts += rs[i]; tq += rq[i]; }

    float mean = ts * (1.0f/1024.0f);
    float var  = (tq - 1024.0f * mean * mean) * (1.0f/1023.0f);  // ddof=1
    float stdv = sqrtf(var);

    float4 gv = *(const float4*)(gamma + tid*4);
    float4 bv = *(const float4*)(beta  + tid*4);
    float4 o4;
    o4.x = gv.x * (x0 - mean) / (stdv + 1e-6f + bv.x);
    o4.y = gv.y * (x1 - mean) / (stdv + 1e-6f + bv.y);
    o4.z = gv.z * (x2 - mean) / (stdv + 1e-6f + bv.z);
    o4.w = gv.w * (x3 - mean) / (stdv + 1e-6f + bv.w);
    *(float4*)(out + (size_t)row * Ee + tid*4) = o4;
}

// ---------------------------------------------------------------------------
// Launch.
// ---------------------------------------------------------------------------
extern "C" void kernel_launch(void* const* d_in, const int* in_sizes, int n_in,
                              void* d_out, int out_size)
{
    (void)in_sizes; (void)n_in; (void)out_size;
    const float* query = (const float*)d_in[0];
    const float* key   = (const float*)d_in[1];
    const float* value = (const float*)d_in[2];
    const float* resid = (const float*)d_in[3];
    const float* Wq = (const float*)d_in[4];
    const float* bq = (const float*)d_in[5];
    const float* Wk = (const float*)d_in[6];
    const float* bk = (const float*)d_in[7];
    const float* Wv = (const float*)d_in[8];
    const float* bv = (const float*)d_in[9];
    const float* gamma = (const float*)d_in[10];
    const float* beta  = (const float*)d_in[11];
    float* out = (float*)d_out;

    const int proj_smem = 4 * STAGE_BYTES;   // 75776
    cudaFuncSetAttribute(proj_kernel,
                         cudaFuncAttributeMaxDynamicSharedMemorySize, proj_smem);

    // cvt: 3*NXE/4 + 3*NWE/4 float4 = 3932160 items -> 15360 blocks
    const int ncvt = (int)((3*NXE/4 + 3*NWE/4 + 255) / 256);
    cvt_kernel<<<ncvt, 256>>>(query, key, value, Wq, Wk, Wv);

    dim3 gproj(32, 8, 3);
    proj_kernel<<<gproj, 256, proj_smem>>>(bq, bk, bv);
    flash_kernel<<<dim3(32, 32, NSPLIT), 128>>>();
    ln_kernel<<<4096, 256>>>(resid, gamma, beta, out);
}

// round 14
// speedup vs baseline: 1.0613x; 1.0039x over previous
#include <cuda_runtime.h>
#include <cuda_bf16.h>
#include <cuda_fp16.h>

// Problem constants
#define Bb 2
#define Ss 2048
#define Ee 1024
#define Hh 16
#define Dd 64
#define SCALE (1.0f/32.0f)   // 1/sqrt(E)
#define NSPLIT 2             // flash key-splits

typedef __nv_bfloat16 bf;

// X region: 3 tensors of Bb*Ss*Ee ; W region: 3 tensors of Hh*Ee*Dd
#define NXE ((size_t)Bb*Ss*Ee)          // 4194304
#define NWE ((size_t)Hh*Ee*Dd)          // 1048576

// ---------------------------------------------------------------------------
// Scratch (device globals; allocation inside kernel_launch is forbidden)
// ---------------------------------------------------------------------------
__device__ bf     g_xw [3*NXE + 3*NWE];         // bf16 pre-converted X then W
__device__ bf     g_q  [(size_t)Bb*Hh*Ss*Dd];   // [b,h,s,d]
__device__ bf     g_kT [(size_t)Bb*Hh*Dd*Ss];   // [b,h,d,s] (transposed K)
__device__ bf     g_v  [(size_t)Bb*Hh*Ss*Dd];   // [b,h,s,d]
__device__ float  g_sk [(size_t)Bb*Hh*Ss];      // 0.5*SCALE*||k||^2 (from proj)
__device__ __half g_po [(size_t)NSPLIT*Bb*Hh*Ss*Dd];  // fp16 unnormalized partials
__device__ float  g_l  [(size_t)NSPLIT*Bb*Hh*Ss];     // partial softmax denoms

// ---------------------------------------------------------------------------
// Helpers
// ---------------------------------------------------------------------------
__device__ __forceinline__ unsigned s2u(const void* p) {
    return (unsigned)__cvta_generic_to_shared(p);
}
__device__ __forceinline__ unsigned f22bf(float x, float y) {
    __nv_bfloat162 h = __floats2bfloat162_rn(x, y);
    return *(unsigned*)&h;
}
__device__ __forceinline__ void mma_bf16(float* c, const unsigned* a, const unsigned* b) {
    asm volatile(
        "mma.sync.aligned.m16n8k16.row.col.f32.bf16.bf16.f32 "
        "{%0,%1,%2,%3}, {%4,%5,%6,%7}, {%8,%9}, {%0,%1,%2,%3};"
        : "+f"(c[0]), "+f"(c[1]), "+f"(c[2]), "+f"(c[3])
        : "r"(a[0]), "r"(a[1]), "r"(a[2]), "r"(a[3]), "r"(b[0]), "r"(b[1]));
}
__device__ __forceinline__ void ldmA(unsigned* a, unsigned saddr) {
    asm volatile("ldmatrix.sync.aligned.m8n8.x4.shared.b16 {%0,%1,%2,%3}, [%4];"
        : "=r"(a[0]), "=r"(a[1]), "=r"(a[2]), "=r"(a[3]) : "r"(saddr));
}
__device__ __forceinline__ void ldmB4(unsigned* b, unsigned saddr) {
    asm volatile("ldmatrix.sync.aligned.m8n8.x4.trans.shared.b16 {%0,%1,%2,%3}, [%4];"
        : "=r"(b[0]), "=r"(b[1]), "=r"(b[2]), "=r"(b[3]) : "r"(saddr));
}
__device__ __forceinline__ void cp16(unsigned dst, const void* src) {
    asm volatile("cp.async.cg.shared.global [%0], [%1], 16;" :: "r"(dst), "l"(src));
}
#define CP_COMMIT()  asm volatile("cp.async.commit_group;")
#define CP_WAIT0()   asm volatile("cp.async.wait_group 0;")
#define CP_WAIT1()   asm volatile("cp.async.wait_group 1;")

// ---------------------------------------------------------------------------
// Kernel 0: fp32 -> bf16 pre-conversion of X (q,k,v inputs) and W (wq,wk,wv).
// ---------------------------------------------------------------------------
__global__ __launch_bounds__(256) void cvt_kernel(
    const float* __restrict__ xq, const float* __restrict__ xk, const float* __restrict__ xv,
    const float* __restrict__ wq, const float* __restrict__ wk, const float* __restrict__ wv)
{
    const size_t NX4 = NXE / 4;          // float4 count per X tensor
    const size_t NW4 = NWE / 4;
    size_t i4 = (size_t)blockIdx.x * 256 + threadIdx.x;
    const float* src;
    bf* dst;
    size_t off;
    if (i4 < 3 * NX4) {
        int z = (int)(i4 / NX4);
        off = (i4 % NX4) * 4;
        src = (z == 0) ? xq : ((z == 1) ? xk : xv);
        dst = g_xw + (size_t)z * NXE;
    } else {
        size_t j4 = i4 - 3 * NX4;
        if (j4 >= 3 * NW4) return;
        int z = (int)(j4 / NW4);
        off = (j4 % NW4) * 4;
        src = (z == 0) ? wq : ((z == 1) ? wk : wv);
        dst = g_xw + 3 * NXE + (size_t)z * NWE;
    }
    float4 v = *(const float4*)(src + off);
    *(uint2*)(dst + off) = make_uint2(f22bf(v.x, v.y), f22bf(v.z, v.w));
}

// ---------------------------------------------------------------------------
// Kernel 1: fused QKV projection, bf16 m16n8k16, cp.async 3-STAGE pipeline
// with K-chunk 64: half the barriers of the 32-chunk version, 64 mma/warp
// between wait-points (~960cyc >> 600cyc LDG latency -> loads fully hidden).
// Block tile 128x128.  z==1 also computes g_sk in its epilogue.
// Dynamic smem: 3 stages x (Xs[128][72] + Ws[64][136]) bf16 = 107520 B.
// ---------------------------------------------------------------------------
#define XS_BYTES (128*72*2)      // 18432
#define WS_BYTES (64*136*2)      // 17408
#define STAGE_BYTES (XS_BYTES + WS_BYTES)   // 35840
#define NCHUNK (Ee/64)           // 16

__global__ __launch_bounds__(256, 2) void proj_kernel(
    const float* __restrict__ Bq, const float* __restrict__ Bk, const float* __restrict__ Bv)
{
    extern __shared__ __align__(16) unsigned char dynsm[];

    const int z = blockIdx.z;
    const bf* Xg = g_xw + (size_t)z * NXE;
    const bf* Wg = g_xw + 3 * NXE + (size_t)z * NWE;
    const float* bias = (z==0) ? Bq : ((z==1) ? Bk : Bv);

    const int tid  = threadIdx.x;
    const int wid  = tid >> 5, lane = tid & 31;
    const int g    = lane >> 2, qd = lane & 3;
    const int wm   = (wid & 1) * 64;
    const int wn   = (wid >> 1) * 32;
    const int m0   = blockIdx.x * 128;
    const int n0   = blockIdx.y * 128;

    const int arow_l = (lane & 7) + ((lane >> 3) & 1) * 8;
    const int acol_l = (lane >> 4) * 8;
    const int brow_l = (lane & 7) + ((lane >> 3) & 1) * 8;
    const int bcol_l = (lane >> 4) * 8;

    // cp.async mapping per stage (K-chunk 64):
    //   X tile [128 rows][64 cols]: 1024 x 16B -> 4 per thread
    //   W tile [64 k-rows][128 cols]: 1024 x 16B -> 4 per thread
    auto issue_loads = [&](int stage, int k0) {
        unsigned char* Xs = dynsm + stage * STAGE_BYTES;
        unsigned char* Ws = Xs + XS_BYTES;
        #pragma unroll
        for (int u = 0; u < 4; u++) {
            int idx = u * 256 + tid;
            int r = idx >> 3, c = (idx & 7) * 8;
            cp16(s2u(Xs + r*144 + c*2), Xg + (size_t)(m0 + r) * Ee + k0 + c);
            int kk = idx >> 4, cw = (idx & 15) * 8;
            int n = n0 + cw, h = n >> 6, d = n & 63;
            cp16(s2u(Ws + kk*272 + cw*2),
                 Wg + (size_t)h * (Ee*Dd) + (size_t)(k0 + kk) * Dd + d);
        }
        CP_COMMIT();
    };

    float acc[4][4][4];
    #pragma unroll
    for (int mi = 0; mi < 4; mi++)
        #pragma unroll
        for (int nj = 0; nj < 4; nj++)
            #pragma unroll
            for (int r = 0; r < 4; r++) acc[mi][nj][r] = 0.f;

    // prologue: stages 0,1 in flight
    issue_loads(0, 0);
    issue_loads(1, 64);

    for (int it = 0; it < NCHUNK; it++) {
        const int stage = it % 3;
        CP_WAIT1();            // group `it` complete (uniform group count)
        __syncthreads();       // all warps done reading stage (it-1)%3
        if (it + 2 < NCHUNK) {
            issue_loads((it + 2) % 3, (it + 2) * 64);
        } else {
            CP_COMMIT();       // empty group keeps the count uniform
        }

        unsigned char* Xs = dynsm + stage * STAGE_BYTES;
        unsigned char* Ws = Xs + XS_BYTES;
        #pragma unroll
        for (int ks = 0; ks < 4; ks++) {
            unsigned a[4][4], b[2][4];
            #pragma unroll
            for (int mi = 0; mi < 4; mi++)
                ldmA(a[mi], s2u(Xs + (wm + mi*16 + arow_l)*144 + (ks*16 + acol_l)*2));
            #pragma unroll
            for (int p = 0; p < 2; p++)
                ldmB4(b[p], s2u(Ws + (ks*16 + brow_l)*272 + (wn + p*16 + bcol_l)*2));
            #pragma unroll
            for (int mi = 0; mi < 4; mi++)
                #pragma unroll
                for (int p = 0; p < 2; p++) {
                    mma_bf16(acc[mi][2*p    ], a[mi], &b[p][0]);
                    mma_bf16(acc[mi][2*p + 1], a[mi], &b[p][2]);
                }
        }
    }

    // Epilogue: +bias, convert/store; z==1 also accumulates row sum-squares
    float rowsq[4][2];
    #pragma unroll
    for (int mi = 0; mi < 4; mi++) { rowsq[mi][0] = 0.f; rowsq[mi][1] = 0.f; }

    #pragma unroll
    for (int mi = 0; mi < 4; mi++) {
        #pragma unroll
        for (int half = 0; half < 2; half++) {
            int m = m0 + wm + mi*16 + g + half*8;
            int bb = m >> 11, s = m & 2047;
            #pragma unroll
            for (int nj = 0; nj < 4; nj++) {
                int n = n0 + wn + nj*8 + 2*qd;
                int h = n >> 6, d = n & 63;
                float v0 = acc[mi][nj][half*2 + 0] + bias[h*Dd + d];
                float v1 = acc[mi][nj][half*2 + 1] + bias[h*Dd + d + 1];
                size_t bh = (size_t)bb * Hh + h;
                if (z == 1) {
                    rowsq[mi][half] = fmaf(v0, v0, rowsq[mi][half]);
                    rowsq[mi][half] = fmaf(v1, v1, rowsq[mi][half]);
                    g_kT[(bh*Dd + d    )*Ss + s] = __float2bfloat16_rn(v0);
                    g_kT[(bh*Dd + d + 1)*Ss + s] = __float2bfloat16_rn(v1);
                } else {
                    bf* out = (z == 0) ? g_q : g_v;
                    *(unsigned*)&out[(bh*Ss + s)*Dd + d] = f22bf(v0, v1);
                }
            }
        }
    }

    if (z == 1) {
        // reduce ||k||^2 per (row, head) and store g_sk
        float* sksum = (float*)dynsm;   // [128][4]; tiles dead after the sync below
        CP_WAIT0();                     // drain pending (possibly empty) groups
        __syncthreads();                // all warps done with smem tiles
        #pragma unroll
        for (int mi = 0; mi < 4; mi++)
            #pragma unroll
            for (int half = 0; half < 2; half++) {
                float v = rowsq[mi][half];
                v += __shfl_xor_sync(0xffffffffu, v, 1);   // quad lanes share the row
                v += __shfl_xor_sync(0xffffffffu, v, 2);
                if (qd == 0)
                    sksum[(wm + mi*16 + g + half*8)*4 + (wid >> 1)] = v;
            }
        __syncthreads();
        {
            int row = tid >> 1, hh = tid & 1;   // 256 threads -> 128 rows x 2 heads
            int m = m0 + row;
            int bb = m >> 11, s = m & 2047;
            float v = sksum[row*4 + 2*hh] + sksum[row*4 + 2*hh + 1];
            int h = (n0 >> 6) + hh;
            g_sk[((size_t)bb*Hh + h)*Ss + s] = 0.5f * SCALE * v;
        }
    }
}

// ---------------------------------------------------------------------------
// Kernel 2: flash attention, bf16 m16n8k16, fixed-max softmax, SPLIT-K (2).
// BQ=64, 4 warps; each block covers 1024 keys.  Writes fp16 UNNORMALIZED
// partial output + fp32 partial l; combine fused into ln_kernel.
// ---------------------------------------------------------------------------
__global__ __launch_bounds__(128) void flash_kernel()
{
    __shared__ __align__(16) unsigned char smbuf[40960];
    bf* Ks[2] = { (bf*)smbuf,            (bf*)(smbuf +  9216) };   // [64][72]
    bf* Vs[2] = { (bf*)(smbuf + 18432),  (bf*)(smbuf + 27648) };   // [64][72]
    float* sks = (float*)(smbuf + 36864);                          // [1024]

    const int bh = blockIdx.y;
    const int q0 = blockIdx.x * 64;
    const int ksp = blockIdx.z;               // 0..NSPLIT-1
    const int kbase = ksp * (Ss / NSPLIT);
    const int tid = threadIdx.x;
    const int wid = tid >> 5, lane = tid & 31;
    const int g = lane >> 2, qd = lane & 3;

    const bf* Qg   = g_q  + ((size_t)bh * Ss + q0) * Dd;
    const bf* KTg  = g_kT + (size_t)bh * Dd * Ss;
    const bf* Vg   = g_v  + (size_t)bh * Ss * Dd;
    const float* skg = g_sk + (size_t)bh * Ss + kbase;

    const int arow_l = (lane & 7) + ((lane >> 3) & 1) * 8;
    const int acol_l = (lane >> 4) * 8;
    const int brow_l = (lane & 7) + ((lane >> 3) & 1) * 8;
    const int bcol_l = (lane >> 4) * 8;
    const int wrow = wid * 16;
    const int crow = wrow + g;

    const int ld_r  = tid >> 3;
    const int ld_c8 = (tid & 7) << 3;

    // ---- Prologue: Q -> staging (Ks[0]) -> A regs; this split's sk row ----
    {
        bf* Qst = Ks[0];
        #pragma unroll
        for (int u = 0; u < 4; u++)
            *(uint4*)&Qst[(ld_r + u*16)*72 + ld_c8] =
                *(const uint4*)(Qg + (size_t)(ld_r + u*16) * Dd + ld_c8);
        #pragma unroll
        for (int u = 0; u < 2; u++) {
            int idx = u * 128 + tid;
            *(float4*)&sks[idx*4] = *(const float4*)(skg + idx*4);
        }
        __syncthreads();
    }
    unsigned qa[4][4];
    #pragma unroll
    for (int t = 0; t < 4; t++)
        ldmA(qa[t], s2u(&Ks[0][(wrow + arow_l)*72 + t*16 + acol_l]));

    // row constants: 0.5*SCALE*||q||^2 for rows crow and crow+8
    float sq0 = 0.f, sq1 = 0.f;
    {
        const bf* r0 = &Ks[0][crow*72];
        const bf* r1 = &Ks[0][(crow+8)*72];
        #pragma unroll
        for (int d = 0; d < Dd; d++) {
            float v0 = __bfloat162float(r0[d]);
            float v1 = __bfloat162float(r1[d]);
            sq0 = fmaf(v0, v0, sq0);
            sq1 = fmaf(v1, v1, sq1);
        }
        sq0 *= 0.5f * SCALE;
        sq1 *= 0.5f * SCALE;
    }
    __syncthreads();   // Q staging dead; cp.async may overwrite

    auto issue_loads = [&](int buf, int k0) {
        #pragma unroll
        for (int u = 0; u < 4; u++) {
            int r = ld_r + u*16;
            cp16(s2u(&Ks[buf][r*72 + ld_c8]), KTg + (size_t)r * Ss + k0 + ld_c8);
            cp16(s2u(&Vs[buf][r*72 + ld_c8]), Vg  + (size_t)(k0 + r) * Dd + ld_c8);
        }
        CP_COMMIT();
    };
    issue_loads(0, kbase);

    float l0 = 0.f, l1 = 0.f;
    float oacc[8][4];
    #pragma unroll
    for (int j = 0; j < 8; j++)
        #pragma unroll
        for (int r = 0; r < 4; r++) oacc[j][r] = 0.f;

    const int NIT = (Ss / NSPLIT) / 64;   // 16
    for (int it = 0; it < NIT; it++) {
        const int k0 = kbase + it * 64;
        const int buf = it & 1;
        CP_WAIT0();
        __syncthreads();
        if (it + 1 < NIT) issue_loads(buf ^ 1, k0 + 64);

        // ---- scores: Q(reg) x K^T[d][key] ----
        float sc[8][4];
        #pragma unroll
        for (int j = 0; j < 8; j++)
            #pragma unroll
            for (int r = 0; r < 4; r++) sc[j][r] = 0.f;

        #pragma unroll
        for (int t = 0; t < 4; t++) {
            #pragma unroll
            for (int p = 0; p < 4; p++) {
                unsigned b[4];
                ldmB4(b, s2u(&Ks[buf][(t*16 + brow_l)*72 + p*16 + bcol_l]));
                mma_bf16(sc[2*p    ], qa[t], &b[0]);
                mma_bf16(sc[2*p + 1], qa[t], &b[2]);
            }
        }

        // ---- exact softmax, fixed max 0: p = exp(qk*SCALE - sk - sq) ----
        #pragma unroll
        for (int j = 0; j < 8; j++) {
            #pragma unroll
            for (int c = 0; c < 2; c++) {
                float skc = sks[it*64 + j*8 + 2*qd + c];
                float p0 = __expf(fmaf(sc[j][c],   SCALE, -skc) - sq0);
                float p1 = __expf(fmaf(sc[j][2+c], SCALE, -skc) - sq1);
                sc[j][c]   = p0; l0 += p0;
                sc[j][2+c] = p1; l1 += p1;
            }
        }

        // ---- PV: P straight from registers (C-frag == A-frag layout) ----
        #pragma unroll
        for (int t = 0; t < 4; t++) {
            unsigned a[4];
            a[0] = f22bf(sc[2*t  ][0], sc[2*t  ][1]);
            a[1] = f22bf(sc[2*t  ][2], sc[2*t  ][3]);
            a[2] = f22bf(sc[2*t+1][0], sc[2*t+1][1]);
            a[3] = f22bf(sc[2*t+1][2], sc[2*t+1][3]);
            #pragma unroll
            for (int p = 0; p < 4; p++) {
                unsigned b[4];
                ldmB4(b, s2u(&Vs[buf][(t*16 + brow_l)*72 + p*16 + bcol_l]));
                mma_bf16(oacc[2*p    ], a, &b[0]);
                mma_bf16(oacc[2*p + 1], a, &b[2]);
            }
        }
    }

    // reduce l across the 4 qd lanes once
    l0 += __shfl_xor_sync(0xffffffffu, l0, 1);
    l0 += __shfl_xor_sync(0xffffffffu, l0, 2);
    l1 += __shfl_xor_sync(0xffffffffu, l1, 1);
    l1 += __shfl_xor_sync(0xffffffffu, l1, 2);

    // Epilogue: fp16 UNNORMALIZED partial out + fp32 l (combined in ln_kernel)
    const int s0 = q0 + crow, s1 = s0 + 8;
    __half* po = g_po + ((size_t)ksp * (Bb*Hh) + bh) * (Ss * Dd);
    #pragma unroll
    for (int j = 0; j < 8; j++) {
        int col = j*8 + 2*qd;
        *(__half2*)&po[(size_t)s0 * Dd + col] = __floats2half2_rn(oacc[j][0], oacc[j][1]);
        *(__half2*)&po[(size_t)s1 * Dd + col] = __floats2half2_rn(oacc[j][2], oacc[j][3]);
    }
    if (qd == 0) {
        float* pl = g_l + ((size_t)ksp * (Bb*Hh) + bh) * Ss;
        pl[s0] = l0;
        pl[s1] = l1;
    }
}

// ---------------------------------------------------------------------------
// Kernel 3: split-combine + residual add + custom LayerNorm.
// ---------------------------------------------------------------------------
__global__ __launch_bounds__(256) void ln_kernel(
    const float* __restrict__ resid, const float* __restrict__ gamma,
    const float* __restrict__ beta, float* __restrict__ out)
{
    const int row = blockIdx.x;            // b*2048 + s
    const int b = row >> 11, s = row & 2047;
    const int tid = threadIdx.x;
    const int h = tid >> 4;
    const int dv4 = (tid & 15) << 2;
    const size_t bh = (size_t)b * Hh + h;

    const __half* po0 = g_po + (bh                ) * (Ss * Dd) + (size_t)s * Dd + dv4;
    const __half* po1 = g_po + ((size_t)Bb*Hh + bh) * (Ss * Dd) + (size_t)s * Dd + dv4;
    float linv = 1.0f / (g_l[bh * Ss + s] + g_l[((size_t)Bb*Hh + bh) * Ss + s]);

    float2 a00 = __half22float2(*(const __half2*)(po0    ));
    float2 a01 = __half22float2(*(const __half2*)(po0 + 2));
    float2 a10 = __half22float2(*(const __half2*)(po1    ));
    float2 a11 = __half22float2(*(const __half2*)(po1 + 2));
    float4 r  = *(const float4*)(resid + (size_t)row * Ee + tid*4);
    float x0 = (a00.x + a10.x) * linv + r.x;
    float x1 = (a00.y + a10.y) * linv + r.y;
    float x2 = (a01.x + a11.x) * linv + r.z;
    float x3 = (a01.y + a11.y) * linv + r.w;

    float sum = x0 + x1 + x2 + x3;
    float sq  = x0*x0 + x1*x1 + x2*x2 + x3*x3;
    #pragma unroll
    for (int o = 16; o >= 1; o >>= 1) {
        sum += __shfl_xor_sync(0xffffffffu, sum, o);
        sq  += __shfl_xor_sync(0xffffffffu, sq,  o);
    }
    __shared__ float rs[8], rq[8];
    int w = tid >> 5, lane = tid & 31;
    if (lane == 0) { rs[w] = sum; rq[w] = sq; }
    __syncthreads();
    float ts = 0.f, tq = 0.f;
    #pragma unroll
    for (int i = 0; i < 8; i++) { ts += rs[i]; tq += rq[i]; }

    float mean = ts * (1.0f/1024.0f);
    float var  = (tq - 1024.0f * mean * mean) * (1.0f/1023.0f);  // ddof=1
    float stdv = sqrtf(var);

    float4 gv = *(const float4*)(gamma + tid*4);
    float4 bv = *(const float4*)(beta  + tid*4);
    float4 o4;
    o4.x = gv.x * (x0 - mean) / (stdv + 1e-6f + bv.x);
    o4.y = gv.y * (x1 - mean) / (stdv + 1e-6f + bv.y);
    o4.z = gv.z * (x2 - mean) / (stdv + 1e-6f + bv.z);
    o4.w = gv.w * (x3 - mean) / (stdv + 1e-6f + bv.w);
    *(float4*)(out + (size_t)row * Ee + tid*4) = o4;
}

// ---------------------------------------------------------------------------
// Launch.
// ---------------------------------------------------------------------------
extern "C" void kernel_launch(void* const* d_in, const int* in_sizes, int n_in,
                              void* d_out, int out_size)
{
    (void)in_sizes; (void)n_in; (void)out_size;
    const float* query = (const float*)d_in[0];
    const float* key   = (const float*)d_in[1];
    const float* value = (const float*)d_in[2];
    const float* resid = (const float*)d_in[3];
    const float* Wq = (const float*)d_in[4];
    const float* bq = (const float*)d_in[5];
    const float* Wk = (const float*)d_in[6];
    const float* bk = (const float*)d_in[7];
    const float* Wv = (const float*)d_in[8];
    const float* bv = (const float*)d_in[9];
    const float* gamma = (const float*)d_in[10];
    const float* beta  = (const float*)d_in[11];
    float* out = (float*)d_out;

    const int proj_smem = 3 * STAGE_BYTES;   // 107520
    cudaFuncSetAttribute(proj_kernel,
                         cudaFuncAttributeMaxDynamicSharedMemorySize, proj_smem);

    const int ncvt = (int)((3*NXE/4 + 3*NWE/4 + 255) / 256);
    cvt_kernel<<<ncvt, 256>>>(query, key, value, Wq, Wk, Wv);

    dim3 gproj(32, 8, 3);
    proj_kernel<<<gproj, 256, proj_smem>>>(bq, bk, bv);
    flash_kernel<<<dim3(32, 32, NSPLIT), 128>>>();
    ln_kernel<<<4096, 256>>>(resid, gamma, beta, out);
}

// round 16
// speedup vs baseline: 1.0789x; 1.0166x over previous
#include <cuda_runtime.h>
#include <cuda_bf16.h>
#include <cuda_fp16.h>

// Problem constants
#define Bb 2
#define Ss 2048
#define Ee 1024
#define Hh 16
#define Dd 64
#define SCALE (1.0f/32.0f)   // 1/sqrt(E)
#define LOG2E 1.44269504f
#define SCL2  (SCALE*LOG2E)  // score scale pre-folded for exp2
#define NSPLIT 2             // flash key-splits

typedef __nv_bfloat16 bf;

// X region: 3 tensors of Bb*Ss*Ee ; W region: 3 tensors of Hh*Ee*Dd
#define NXE ((size_t)Bb*Ss*Ee)          // 4194304
#define NWE ((size_t)Hh*Ee*Dd)          // 1048576

// ---------------------------------------------------------------------------
// Scratch (device globals; allocation inside kernel_launch is forbidden)
// ---------------------------------------------------------------------------
__device__ bf     g_xw [3*NXE + 3*NWE];         // bf16 pre-converted X then W
__device__ bf     g_q  [(size_t)Bb*Hh*Ss*Dd];   // [b,h,s,d]
__device__ bf     g_kT [(size_t)Bb*Hh*Dd*Ss];   // [b,h,d,s] (transposed K)
__device__ bf     g_v  [(size_t)Bb*Hh*Ss*Dd];   // [b,h,s,d]
__device__ float  g_sk [(size_t)Bb*Hh*Ss];      // 0.5*SCALE*LOG2E*||k||^2
__device__ __half g_po [(size_t)NSPLIT*Bb*Hh*Ss*Dd];  // fp16 unnormalized partials
__device__ float  g_l  [(size_t)NSPLIT*Bb*Hh*Ss];     // partial softmax denoms

// ---------------------------------------------------------------------------
// Helpers
// ---------------------------------------------------------------------------
__device__ __forceinline__ unsigned s2u(const void* p) {
    return (unsigned)__cvta_generic_to_shared(p);
}
__device__ __forceinline__ unsigned f22bf(float x, float y) {
    __nv_bfloat162 h = __floats2bfloat162_rn(x, y);
    return *(unsigned*)&h;
}
__device__ __forceinline__ void mma_bf16(float* c, const unsigned* a, const unsigned* b) {
    asm volatile(
        "mma.sync.aligned.m16n8k16.row.col.f32.bf16.bf16.f32 "
        "{%0,%1,%2,%3}, {%4,%5,%6,%7}, {%8,%9}, {%0,%1,%2,%3};"
        : "+f"(c[0]), "+f"(c[1]), "+f"(c[2]), "+f"(c[3])
        : "r"(a[0]), "r"(a[1]), "r"(a[2]), "r"(a[3]), "r"(b[0]), "r"(b[1]));
}
__device__ __forceinline__ void ldmA(unsigned* a, unsigned saddr) {
    asm volatile("ldmatrix.sync.aligned.m8n8.x4.shared.b16 {%0,%1,%2,%3}, [%4];"
        : "=r"(a[0]), "=r"(a[1]), "=r"(a[2]), "=r"(a[3]) : "r"(saddr));
}
__device__ __forceinline__ void ldmB4(unsigned* b, unsigned saddr) {
    asm volatile("ldmatrix.sync.aligned.m8n8.x4.trans.shared.b16 {%0,%1,%2,%3}, [%4];"
        : "=r"(b[0]), "=r"(b[1]), "=r"(b[2]), "=r"(b[3]) : "r"(saddr));
}
__device__ __forceinline__ void cp16(unsigned dst, const void* src) {
    asm volatile("cp.async.cg.shared.global [%0], [%1], 16;" :: "r"(dst), "l"(src));
}
#define CP_COMMIT()  asm volatile("cp.async.commit_group;")
#define CP_WAIT0()   asm volatile("cp.async.wait_group 0;")
#define CP_WAIT1()   asm volatile("cp.async.wait_group 1;")

// ---------------------------------------------------------------------------
// Kernel 0: fp32 -> bf16 pre-conversion of X (q,k,v inputs) and W (wq,wk,wv).
// ---------------------------------------------------------------------------
__global__ __launch_bounds__(256) void cvt_kernel(
    const float* __restrict__ xq, const float* __restrict__ xk, const float* __restrict__ xv,
    const float* __restrict__ wq, const float* __restrict__ wk, const float* __restrict__ wv)
{
    const size_t NX4 = NXE / 4;
    const size_t NW4 = NWE / 4;
    size_t i4 = (size_t)blockIdx.x * 256 + threadIdx.x;
    const float* src;
    bf* dst;
    size_t off;
    if (i4 < 3 * NX4) {
        int z = (int)(i4 / NX4);
        off = (i4 % NX4) * 4;
        src = (z == 0) ? xq : ((z == 1) ? xk : xv);
        dst = g_xw + (size_t)z * NXE;
    } else {
        size_t j4 = i4 - 3 * NX4;
        if (j4 >= 3 * NW4) return;
        int z = (int)(j4 / NW4);
        off = (j4 % NW4) * 4;
        src = (z == 0) ? wq : ((z == 1) ? wk : wv);
        dst = g_xw + 3 * NXE + (size_t)z * NWE;
    }
    float4 v = *(const float4*)(src + off);
    *(uint2*)(dst + off) = make_uint2(f22bf(v.x, v.y), f22bf(v.z, v.w));
}

// ---------------------------------------------------------------------------
// Kernel 1: fused QKV projection, bf16 m16n8k16, cp.async 3-STAGE K-chunk-64
// pipeline.  z==1: kT stored via SMEM TRANSPOSE STAGE (coalesced 16B rows
// along s instead of scattered 2B stores) and g_sk computed in the epilogue
// (pre-scaled by LOG2E for flash's exp2).
// Dynamic smem: 3 x (Xs[128][72] + Ws[64][136]) bf16 = 107520 B.
// ---------------------------------------------------------------------------
#define XS_BYTES (128*72*2)      // 18432
#define WS_BYTES (64*136*2)      // 17408
#define STAGE_BYTES (XS_BYTES + WS_BYTES)   // 35840
#define NCHUNK (Ee/64)           // 16

__global__ __launch_bounds__(256, 2) void proj_kernel(
    const float* __restrict__ Bq, const float* __restrict__ Bk, const float* __restrict__ Bv)
{
    extern __shared__ __align__(16) unsigned char dynsm[];

    const int z = blockIdx.z;
    const bf* Xg = g_xw + (size_t)z * NXE;
    const bf* Wg = g_xw + 3 * NXE + (size_t)z * NWE;
    const float* bias = (z==0) ? Bq : ((z==1) ? Bk : Bv);

    const int tid  = threadIdx.x;
    const int wid  = tid >> 5, lane = tid & 31;
    const int g    = lane >> 2, qd = lane & 3;
    const int wm   = (wid & 1) * 64;
    const int wn   = (wid >> 1) * 32;
    const int m0   = blockIdx.x * 128;
    const int n0   = blockIdx.y * 128;

    const int arow_l = (lane & 7) + ((lane >> 3) & 1) * 8;
    const int acol_l = (lane >> 4) * 8;
    const int brow_l = (lane & 7) + ((lane >> 3) & 1) * 8;
    const int bcol_l = (lane >> 4) * 8;

    auto issue_loads = [&](int stage, int k0) {
        unsigned char* Xs = dynsm + stage * STAGE_BYTES;
        unsigned char* Ws = Xs + XS_BYTES;
        #pragma unroll
        for (int u = 0; u < 4; u++) {
            int idx = u * 256 + tid;
            int r = idx >> 3, c = (idx & 7) * 8;
            cp16(s2u(Xs + r*144 + c*2), Xg + (size_t)(m0 + r) * Ee + k0 + c);
            int kk = idx >> 4, cw = (idx & 15) * 8;
            int n = n0 + cw, h = n >> 6, d = n & 63;
            cp16(s2u(Ws + kk*272 + cw*2),
                 Wg + (size_t)h * (Ee*Dd) + (size_t)(k0 + kk) * Dd + d);
        }
        CP_COMMIT();
    };

    float acc[4][4][4];
    #pragma unroll
    for (int mi = 0; mi < 4; mi++)
        #pragma unroll
        for (int nj = 0; nj < 4; nj++)
            #pragma unroll
            for (int r = 0; r < 4; r++) acc[mi][nj][r] = 0.f;

    issue_loads(0, 0);
    issue_loads(1, 64);

    for (int it = 0; it < NCHUNK; it++) {
        const int stage = it % 3;
        CP_WAIT1();
        __syncthreads();
        if (it + 2 < NCHUNK) {
            issue_loads((it + 2) % 3, (it + 2) * 64);
        } else {
            CP_COMMIT();       // empty group keeps the count uniform
        }

        unsigned char* Xs = dynsm + stage * STAGE_BYTES;
        unsigned char* Ws = Xs + XS_BYTES;
        #pragma unroll
        for (int ks = 0; ks < 4; ks++) {
            unsigned a[4][4], b[2][4];
            #pragma unroll
            for (int mi = 0; mi < 4; mi++)
                ldmA(a[mi], s2u(Xs + (wm + mi*16 + arow_l)*144 + (ks*16 + acol_l)*2));
            #pragma unroll
            for (int p = 0; p < 2; p++)
                ldmB4(b[p], s2u(Ws + (ks*16 + brow_l)*272 + (wn + p*16 + bcol_l)*2));
            #pragma unroll
            for (int mi = 0; mi < 4; mi++)
                #pragma unroll
                for (int p = 0; p < 2; p++) {
                    mma_bf16(acc[mi][2*p    ], a[mi], &b[p][0]);
                    mma_bf16(acc[mi][2*p + 1], a[mi], &b[p][2]);
                }
        }
    }

    // ---- Epilogue ----
    if (z == 1) {
        // K path: stage transposed tile in smem, coalesced store + ||k||^2.
        CP_WAIT0();          // drain pending (empty) groups
        __syncthreads();     // pipeline buffers dead -> reuse dynsm
        bf* kTs = (bf*)dynsm;                    // [128 n][136 pitch] bf16 = 34816B
        float* sksum = (float*)(dynsm + 65536);  // [128][4]

        float rowsq[4][2];
        #pragma unroll
        for (int mi = 0; mi < 4; mi++) { rowsq[mi][0] = 0.f; rowsq[mi][1] = 0.f; }

        #pragma unroll
        for (int mi = 0; mi < 4; mi++) {
            #pragma unroll
            for (int half = 0; half < 2; half++) {
                int mloc = wm + mi*16 + g + half*8;
                #pragma unroll
                for (int nj = 0; nj < 4; nj++) {
                    int nloc = wn + nj*8 + 2*qd;
                    int n = n0 + nloc;
                    int h = n >> 6, d = n & 63;
                    float v0 = acc[mi][nj][half*2 + 0] + bias[h*Dd + d];
                    float v1 = acc[mi][nj][half*2 + 1] + bias[h*Dd + d + 1];
                    rowsq[mi][half] = fmaf(v0, v0, rowsq[mi][half]);
                    rowsq[mi][half] = fmaf(v1, v1, rowsq[mi][half]);
                    kTs[ nloc     *136 + mloc] = __float2bfloat16_rn(v0);
                    kTs[(nloc + 1)*136 + mloc] = __float2bfloat16_rn(v1);
                }
            }
        }
        // ||k||^2 reduction (quad lanes share a row)
        #pragma unroll
        for (int mi = 0; mi < 4; mi++)
            #pragma unroll
            for (int half = 0; half < 2; half++) {
                float v = rowsq[mi][half];
                v += __shfl_xor_sync(0xffffffffu, v, 1);
                v += __shfl_xor_sync(0xffffffffu, v, 2);
                if (qd == 0)
                    sksum[(wm + mi*16 + g + half*8)*4 + (wid >> 1)] = v;
            }
        __syncthreads();

        // coalesced kT store: row r = (h_loc, d) -> 128 s-values contiguous
        const int bb = m0 >> 11, sbase = m0 & 2047;
        #pragma unroll
        for (int u = 0; u < 8; u++) {
            int idx = u * 256 + tid;           // 0..2047
            int r = idx >> 4, c16 = (idx & 15) * 8;
            int h = (n0 >> 6) + (r >> 6), d = r & 63;
            uint4 v = *(uint4*)&kTs[r*136 + c16];
            *(uint4*)&g_kT[(((size_t)bb*Hh + h)*Dd + d)*Ss + sbase + c16] = v;
        }
        // g_sk (pre-scaled by LOG2E for flash's exp2)
        {
            int row = tid >> 1, hh = tid & 1;
            float v = sksum[row*4 + 2*hh] + sksum[row*4 + 2*hh + 1];
            int h = (n0 >> 6) + hh;
            g_sk[((size_t)bb*Hh + h)*Ss + sbase + row] = 0.5f * SCL2 * v;
        }
    } else {
        #pragma unroll
        for (int mi = 0; mi < 4; mi++) {
            #pragma unroll
            for (int half = 0; half < 2; half++) {
                int m = m0 + wm + mi*16 + g + half*8;
                int bb = m >> 11, s = m & 2047;
                #pragma unroll
                for (int nj = 0; nj < 4; nj++) {
                    int n = n0 + wn + nj*8 + 2*qd;
                    int h = n >> 6, d = n & 63;
                    float v0 = acc[mi][nj][half*2 + 0] + bias[h*Dd + d];
                    float v1 = acc[mi][nj][half*2 + 1] + bias[h*Dd + d + 1];
                    size_t bh = (size_t)bb * Hh + h;
                    bf* out = (z == 0) ? g_q : g_v;
                    *(unsigned*)&out[(bh*Ss + s)*Dd + d] = f22bf(v0, v1);
                }
            }
        }
    }
}

// ---------------------------------------------------------------------------
// Kernel 2: flash attention, bf16 m16n8k16, fixed-max softmax (exp2 path),
// SPLIT-K (2).  BQ=64, 4 warps.  fp16 unnormalized partials + fp32 l.
// ---------------------------------------------------------------------------
__global__ __launch_bounds__(128) void flash_kernel()
{
    __shared__ __align__(16) unsigned char smbuf[40960];
    bf* Ks[2] = { (bf*)smbuf,            (bf*)(smbuf +  9216) };   // [64][72]
    bf* Vs[2] = { (bf*)(smbuf + 18432),  (bf*)(smbuf + 27648) };   // [64][72]
    float* sks = (float*)(smbuf + 36864);                          // [1024]

    const int bh = blockIdx.y;
    const int q0 = blockIdx.x * 64;
    const int ksp = blockIdx.z;
    const int kbase = ksp * (Ss / NSPLIT);
    const int tid = threadIdx.x;
    const int wid = tid >> 5, lane = tid & 31;
    const int g = lane >> 2, qd = lane & 3;

    const bf* Qg   = g_q  + ((size_t)bh * Ss + q0) * Dd;
    const bf* KTg  = g_kT + (size_t)bh * Dd * Ss;
    const bf* Vg   = g_v  + (size_t)bh * Ss * Dd;
    const float* skg = g_sk + (size_t)bh * Ss + kbase;

    const int arow_l = (lane & 7) + ((lane >> 3) & 1) * 8;
    const int acol_l = (lane >> 4) * 8;
    const int brow_l = (lane & 7) + ((lane >> 3) & 1) * 8;
    const int bcol_l = (lane >> 4) * 8;
    const int wrow = wid * 16;
    const int crow = wrow + g;

    const int ld_r  = tid >> 3;
    const int ld_c8 = (tid & 7) << 3;

    // ---- Prologue: Q -> staging (Ks[0]) -> A regs; this split's sk row ----
    {
        bf* Qst = Ks[0];
        #pragma unroll
        for (int u = 0; u < 4; u++)
            *(uint4*)&Qst[(ld_r + u*16)*72 + ld_c8] =
                *(const uint4*)(Qg + (size_t)(ld_r + u*16) * Dd + ld_c8);
        #pragma unroll
        for (int u = 0; u < 2; u++) {
            int idx = u * 128 + tid;
            *(float4*)&sks[idx*4] = *(const float4*)(skg + idx*4);
        }
        __syncthreads();
    }
    unsigned qa[4][4];
    #pragma unroll
    for (int t = 0; t < 4; t++)
        ldmA(qa[t], s2u(&Ks[0][(wrow + arow_l)*72 + t*16 + acol_l]));

    // row constants: 0.5*SCL2*||q||^2 for rows crow and crow+8
    float sq0 = 0.f, sq1 = 0.f;
    {
        const bf* r0 = &Ks[0][crow*72];
        const bf* r1 = &Ks[0][(crow+8)*72];
        #pragma unroll
        for (int d = 0; d < Dd; d++) {
            float v0 = __bfloat162float(r0[d]);
            float v1 = __bfloat162float(r1[d]);
            sq0 = fmaf(v0, v0, sq0);
            sq1 = fmaf(v1, v1, sq1);
        }
        sq0 *= 0.5f * SCL2;
        sq1 *= 0.5f * SCL2;
    }
    __syncthreads();   // Q staging dead; cp.async may overwrite

    auto issue_loads = [&](int buf, int k0) {
        #pragma unroll
        for (int u = 0; u < 4; u++) {
            int r = ld_r + u*16;
            cp16(s2u(&Ks[buf][r*72 + ld_c8]), KTg + (size_t)r * Ss + k0 + ld_c8);
            cp16(s2u(&Vs[buf][r*72 + ld_c8]), Vg  + (size_t)(k0 + r) * Dd + ld_c8);
        }
        CP_COMMIT();
    };
    issue_loads(0, kbase);

    float l0 = 0.f, l1 = 0.f;
    float oacc[8][4];
    #pragma unroll
    for (int j = 0; j < 8; j++)
        #pragma unroll
        for (int r = 0; r < 4; r++) oacc[j][r] = 0.f;

    const int NIT = (Ss / NSPLIT) / 64;   // 16
    for (int it = 0; it < NIT; it++) {
        const int k0 = kbase + it * 64;
        const int buf = it & 1;
        CP_WAIT0();
        __syncthreads();
        if (it + 1 < NIT) issue_loads(buf ^ 1, k0 + 64);

        // ---- scores: Q(reg) x K^T[d][key] ----
        float sc[8][4];
        #pragma unroll
        for (int j = 0; j < 8; j++)
            #pragma unroll
            for (int r = 0; r < 4; r++) sc[j][r] = 0.f;

        #pragma unroll
        for (int t = 0; t < 4; t++) {
            #pragma unroll
            for (int p = 0; p < 4; p++) {
                unsigned b[4];
                ldmB4(b, s2u(&Ks[buf][(t*16 + brow_l)*72 + p*16 + bcol_l]));
                mma_bf16(sc[2*p    ], qa[t], &b[0]);
                mma_bf16(sc[2*p + 1], qa[t], &b[2]);
            }
        }

        // ---- exact softmax, fixed max 0, exp2 path (sk/sq pre-scaled) ----
        #pragma unroll
        for (int j = 0; j < 8; j++) {
            #pragma unroll
            for (int c = 0; c < 2; c++) {
                float skc = sks[it*64 + j*8 + 2*qd + c];
                float p0 = exp2f(fmaf(sc[j][c],   SCL2, -skc) - sq0);
                float p1 = exp2f(fmaf(sc[j][2+c], SCL2, -skc) - sq1);
                sc[j][c]   = p0; l0 += p0;
                sc[j][2+c] = p1; l1 += p1;
            }
        }

        // ---- PV: P straight from registers (C-frag == A-frag layout) ----
        #pragma unroll
        for (int t = 0; t < 4; t++) {
            unsigned a[4];
            a[0] = f22bf(sc[2*t  ][0], sc[2*t  ][1]);
            a[1] = f22bf(sc[2*t  ][2], sc[2*t  ][3]);
            a[2] = f22bf(sc[2*t+1][0], sc[2*t+1][1]);
            a[3] = f22bf(sc[2*t+1][2], sc[2*t+1][3]);
            #pragma unroll
            for (int p = 0; p < 4; p++) {
                unsigned b[4];
                ldmB4(b, s2u(&Vs[buf][(t*16 + brow_l)*72 + p*16 + bcol_l]));
                mma_bf16(oacc[2*p    ], a, &b[0]);
                mma_bf16(oacc[2*p + 1], a, &b[2]);
            }
        }
    }

    // reduce l across the 4 qd lanes once
    l0 += __shfl_xor_sync(0xffffffffu, l0, 1);
    l0 += __shfl_xor_sync(0xffffffffu, l0, 2);
    l1 += __shfl_xor_sync(0xffffffffu, l1, 1);
    l1 += __shfl_xor_sync(0xffffffffu, l1, 2);

    // Epilogue: fp16 UNNORMALIZED partial out + fp32 l (combined in ln_kernel)
    const int s0 = q0 + crow, s1 = s0 + 8;
    __half* po = g_po + ((size_t)ksp * (Bb*Hh) + bh) * (Ss * Dd);
    #pragma unroll
    for (int j = 0; j < 8; j++) {
        int col = j*8 + 2*qd;
        *(__half2*)&po[(size_t)s0 * Dd + col] = __floats2half2_rn(oacc[j][0], oacc[j][1]);
        *(__half2*)&po[(size_t)s1 * Dd + col] = __floats2half2_rn(oacc[j][2], oacc[j][3]);
    }
    if (qd == 0) {
        float* pl = g_l + ((size_t)ksp * (Bb*Hh) + bh) * Ss;
        pl[s0] = l0;
        pl[s1] = l1;
    }
}

// ---------------------------------------------------------------------------
// Kernel 3: split-combine + residual add + custom LayerNorm.
// ---------------------------------------------------------------------------
__global__ __launch_bounds__(256) void ln_kernel(
    const float* __restrict__ resid, const float* __restrict__ gamma,
    const float* __restrict__ beta, float* __restrict__ out)
{
    const int row = blockIdx.x;            // b*2048 + s
    const int b = row >> 11, s = row & 2047;
    const int tid = threadIdx.x;
    const int h = tid >> 4;
    const int dv4 = (tid & 15) << 2;
    const size_t bh = (size_t)b * Hh + h;

    const __half* po0 = g_po + (bh                ) * (Ss * Dd) + (size_t)s * Dd + dv4;
    const __half* po1 = g_po + ((size_t)Bb*Hh + bh) * (Ss * Dd) + (size_t)s * Dd + dv4;
    float linv = 1.0f / (g_l[bh * Ss + s] + g_l[((size_t)Bb*Hh + bh) * Ss + s]);

    float2 a00 = __half22float2(*(const __half2*)(po0    ));
    float2 a01 = __half22float2(*(const __half2*)(po0 + 2));
    float2 a10 = __half22float2(*(const __half2*)(po1    ));
    float2 a11 = __half22float2(*(const __half2*)(po1 + 2));
    float4 r  = *(const float4*)(resid + (size_t)row * Ee + tid*4);
    float x0 = (a00.x + a10.x) * linv + r.x;
    float x1 = (a00.y + a10.y) * linv + r.y;
    float x2 = (a01.x + a11.x) * linv + r.z;
    float x3 = (a01.y + a11.y) * linv + r.w;

    float sum = x0 + x1 + x2 + x3;
    float sq  = x0*x0 + x1*x1 + x2*x2 + x3*x3;
    #pragma unroll
    for (int o = 16; o >= 1; o >>= 1) {
        sum += __shfl_xor_sync(0xffffffffu, sum, o);
        sq  += __shfl_xor_sync(0xffffffffu, sq,  o);
    }
    __shared__ float rs[8], rq[8];
    int w = tid >> 5, lane = tid & 31;
    if (lane == 0) { rs[w] = sum; rq[w] = sq; }
    __syncthreads();
    float ts = 0.f, tq = 0.f;
    #pragma unroll
    for (int i = 0; i < 8; i++) { ts += rs[i]; tq += rq[i]; }

    float mean = ts * (1.0f/1024.0f);
    float var  = (tq - 1024.0f * mean * mean) * (1.0f/1023.0f);  // ddof=1
    float stdv = sqrtf(var);

    float4 gv = *(const float4*)(gamma + tid*4);
    float4 bv = *(const float4*)(beta  + tid*4);
    float4 o4;
    o4.x = gv.x * (x0 - mean) / (stdv + 1e-6f + bv.x);
    o4.y = gv.y * (x1 - mean) / (stdv + 1e-6f + bv.y);
    o4.z = gv.z * (x2 - mean) / (stdv + 1e-6f + bv.z);
    o4.w = gv.w * (x3 - mean) / (stdv + 1e-6f + bv.w);
    *(float4*)(out + (size_t)row * Ee + tid*4) = o4;
}

// ---------------------------------------------------------------------------
// Launch.
// ---------------------------------------------------------------------------
extern "C" void kernel_launch(void* const* d_in, const int* in_sizes, int n_in,
                              void* d_out, int out_size)
{
    (void)in_sizes; (void)n_in; (void)out_size;
    const float* query = (const float*)d_in[0];
    const float* key   = (const float*)d_in[1];
    const float* value = (const float*)d_in[2];
    const float* resid = (const float*)d_in[3];
    const float* Wq = (const float*)d_in[4];
    const float* bq = (const float*)d_in[5];
    const float* Wk = (const float*)d_in[6];
    const float* bk = (const float*)d_in[7];
    const float* Wv = (const float*)d_in[8];
    const float* bv = (const float*)d_in[9];
    const float* gamma = (const float*)d_in[10];
    const float* beta  = (const float*)d_in[11];
    float* out = (float*)d_out;

    const int proj_smem = 3 * STAGE_BYTES;   // 107520
    cudaFuncSetAttribute(proj_kernel,
                         cudaFuncAttributeMaxDynamicSharedMemorySize, proj_smem);

    const int ncvt = (int)((3*NXE/4 + 3*NWE/4 + 255) / 256);
    cvt_kernel<<<ncvt, 256>>>(query, key, value, Wq, Wk, Wv);

    dim3 gproj(32, 8, 3);
    proj_kernel<<<gproj, 256, proj_smem>>>(bq, bk, bv);
    flash_kernel<<<dim3(32, 32, NSPLIT), 128>>>();
    ln_kernel<<<4096, 256>>>(resid, gamma, beta, out);
}

// round 17
// speedup vs baseline: 1.0936x; 1.0136x over previous
#include <cuda_runtime.h>
#include <cuda_bf16.h>
#include <cuda_fp16.h>

// Problem constants
#define Bb 2
#define Ss 2048
#define Ee 1024
#define Hh 16
#define Dd 64
#define SCALE (1.0f/32.0f)   // 1/sqrt(E)
#define LOG2E 1.44269504f
#define SCL2  (SCALE*LOG2E)  // score scale pre-folded for exp2
#define NSPLIT 2             // flash key-splits

typedef __nv_bfloat16 bf;

// X region: 3 tensors of Bb*Ss*Ee ; W region: 3 tensors of Hh*Ee*Dd
#define NXE ((size_t)Bb*Ss*Ee)          // 4194304
#define NWE ((size_t)Hh*Ee*Dd)          // 1048576

// ---------------------------------------------------------------------------
// Scratch (device globals; allocation inside kernel_launch is forbidden)
// ---------------------------------------------------------------------------
__device__ bf     g_xw [3*NXE + 3*NWE];         // bf16 pre-converted X then W
__device__ bf     g_q  [(size_t)Bb*Hh*Ss*Dd];   // [b,h,s,d]
__device__ bf     g_kT [(size_t)Bb*Hh*Dd*Ss];   // [b,h,d,s] (transposed K)
__device__ bf     g_v  [(size_t)Bb*Hh*Ss*Dd];   // [b,h,s,d]
__device__ float  g_sk [(size_t)Bb*Hh*Ss];      // 0.5*SCL2*||k||^2
__device__ __half g_po [(size_t)NSPLIT*Bb*Hh*Ss*Dd];  // fp16 unnormalized partials
__device__ float  g_l  [(size_t)NSPLIT*Bb*Hh*Ss];     // partial softmax denoms

// ---------------------------------------------------------------------------
// Helpers
// ---------------------------------------------------------------------------
__device__ __forceinline__ unsigned s2u(const void* p) {
    return (unsigned)__cvta_generic_to_shared(p);
}
__device__ __forceinline__ unsigned f22bf(float x, float y) {
    __nv_bfloat162 h = __floats2bfloat162_rn(x, y);
    return *(unsigned*)&h;
}
__device__ __forceinline__ void mma_bf16(float* c, const unsigned* a, const unsigned* b) {
    asm volatile(
        "mma.sync.aligned.m16n8k16.row.col.f32.bf16.bf16.f32 "
        "{%0,%1,%2,%3}, {%4,%5,%6,%7}, {%8,%9}, {%0,%1,%2,%3};"
        : "+f"(c[0]), "+f"(c[1]), "+f"(c[2]), "+f"(c[3])
        : "r"(a[0]), "r"(a[1]), "r"(a[2]), "r"(a[3]), "r"(b[0]), "r"(b[1]));
}
__device__ __forceinline__ void ldmA(unsigned* a, unsigned saddr) {
    asm volatile("ldmatrix.sync.aligned.m8n8.x4.shared.b16 {%0,%1,%2,%3}, [%4];"
        : "=r"(a[0]), "=r"(a[1]), "=r"(a[2]), "=r"(a[3]) : "r"(saddr));
}
__device__ __forceinline__ void ldmB4(unsigned* b, unsigned saddr) {
    asm volatile("ldmatrix.sync.aligned.m8n8.x4.trans.shared.b16 {%0,%1,%2,%3}, [%4];"
        : "=r"(b[0]), "=r"(b[1]), "=r"(b[2]), "=r"(b[3]) : "r"(saddr));
}
__device__ __forceinline__ void cp16(unsigned dst, const void* src) {
    asm volatile("cp.async.cg.shared.global [%0], [%1], 16;" :: "r"(dst), "l"(src));
}
#define CP_COMMIT()  asm volatile("cp.async.commit_group;")
#define CP_WAIT0()   asm volatile("cp.async.wait_group 0;")
#define CP_WAIT1()   asm volatile("cp.async.wait_group 1;")

// ---------------------------------------------------------------------------
// Kernel 0: fp32 -> bf16 pre-conversion of X (q,k,v inputs) and W (wq,wk,wv).
// ---------------------------------------------------------------------------
__global__ __launch_bounds__(256) void cvt_kernel(
    const float* __restrict__ xq, const float* __restrict__ xk, const float* __restrict__ xv,
    const float* __restrict__ wq, const float* __restrict__ wk, const float* __restrict__ wv)
{
    const size_t NX4 = NXE / 4;
    const size_t NW4 = NWE / 4;
    size_t i4 = (size_t)blockIdx.x * 256 + threadIdx.x;
    const float* src;
    bf* dst;
    size_t off;
    if (i4 < 3 * NX4) {
        int z = (int)(i4 / NX4);
        off = (i4 % NX4) * 4;
        src = (z == 0) ? xq : ((z == 1) ? xk : xv);
        dst = g_xw + (size_t)z * NXE;
    } else {
        size_t j4 = i4 - 3 * NX4;
        if (j4 >= 3 * NW4) return;
        int z = (int)(j4 / NW4);
        off = (j4 % NW4) * 4;
        src = (z == 0) ? wq : ((z == 1) ? wk : wv);
        dst = g_xw + 3 * NXE + (size_t)z * NWE;
    }
    float4 v = *(const float4*)(src + off);
    *(uint2*)(dst + off) = make_uint2(f22bf(v.x, v.y), f22bf(v.z, v.w));
}

// ---------------------------------------------------------------------------
// Kernel 1: fused QKV projection, bf16 m16n8k16, cp.async 3-STAGE K-chunk-64
// pipeline.  ALL epilogues staged through smem for coalesced 16B stores:
// z==1 transposed (kT) + g_sk (pre-scaled by LOG2E); z==0/2 direct layout.
// Dynamic smem: 3 x (Xs[128][72] + Ws[64][136]) bf16 = 107520 B.
// ---------------------------------------------------------------------------
#define XS_BYTES (128*72*2)      // 18432
#define WS_BYTES (64*136*2)      // 17408
#define STAGE_BYTES (XS_BYTES + WS_BYTES)   // 35840
#define NCHUNK (Ee/64)           // 16

__global__ __launch_bounds__(256, 2) void proj_kernel(
    const float* __restrict__ Bq, const float* __restrict__ Bk, const float* __restrict__ Bv)
{
    extern __shared__ __align__(16) unsigned char dynsm[];

    const int z = blockIdx.z;
    const bf* Xg = g_xw + (size_t)z * NXE;
    const bf* Wg = g_xw + 3 * NXE + (size_t)z * NWE;
    const float* bias = (z==0) ? Bq : ((z==1) ? Bk : Bv);

    const int tid  = threadIdx.x;
    const int wid  = tid >> 5, lane = tid & 31;
    const int g    = lane >> 2, qd = lane & 3;
    const int wm   = (wid & 1) * 64;
    const int wn   = (wid >> 1) * 32;
    const int m0   = blockIdx.x * 128;
    const int n0   = blockIdx.y * 128;

    const int arow_l = (lane & 7) + ((lane >> 3) & 1) * 8;
    const int acol_l = (lane >> 4) * 8;
    const int brow_l = (lane & 7) + ((lane >> 3) & 1) * 8;
    const int bcol_l = (lane >> 4) * 8;

    auto issue_loads = [&](int stage, int k0) {
        unsigned char* Xs = dynsm + stage * STAGE_BYTES;
        unsigned char* Ws = Xs + XS_BYTES;
        #pragma unroll
        for (int u = 0; u < 4; u++) {
            int idx = u * 256 + tid;
            int r = idx >> 3, c = (idx & 7) * 8;
            cp16(s2u(Xs + r*144 + c*2), Xg + (size_t)(m0 + r) * Ee + k0 + c);
            int kk = idx >> 4, cw = (idx & 15) * 8;
            int n = n0 + cw, h = n >> 6, d = n & 63;
            cp16(s2u(Ws + kk*272 + cw*2),
                 Wg + (size_t)h * (Ee*Dd) + (size_t)(k0 + kk) * Dd + d);
        }
        CP_COMMIT();
    };

    float acc[4][4][4];
    #pragma unroll
    for (int mi = 0; mi < 4; mi++)
        #pragma unroll
        for (int nj = 0; nj < 4; nj++)
            #pragma unroll
            for (int r = 0; r < 4; r++) acc[mi][nj][r] = 0.f;

    issue_loads(0, 0);
    issue_loads(1, 64);

    for (int it = 0; it < NCHUNK; it++) {
        const int stage = it % 3;
        CP_WAIT1();
        __syncthreads();
        if (it + 2 < NCHUNK) {
            issue_loads((it + 2) % 3, (it + 2) * 64);
        } else {
            CP_COMMIT();       // empty group keeps the count uniform
        }

        unsigned char* Xs = dynsm + stage * STAGE_BYTES;
        unsigned char* Ws = Xs + XS_BYTES;
        #pragma unroll
        for (int ks = 0; ks < 4; ks++) {
            unsigned a[4][4], b[2][4];
            #pragma unroll
            for (int mi = 0; mi < 4; mi++)
                ldmA(a[mi], s2u(Xs + (wm + mi*16 + arow_l)*144 + (ks*16 + acol_l)*2));
            #pragma unroll
            for (int p = 0; p < 2; p++)
                ldmB4(b[p], s2u(Ws + (ks*16 + brow_l)*272 + (wn + p*16 + bcol_l)*2));
            #pragma unroll
            for (int mi = 0; mi < 4; mi++)
                #pragma unroll
                for (int p = 0; p < 2; p++) {
                    mma_bf16(acc[mi][2*p    ], a[mi], &b[p][0]);
                    mma_bf16(acc[mi][2*p + 1], a[mi], &b[p][2]);
                }
        }
    }

    // ---- Epilogue (all z staged through smem for coalesced stores) ----
    CP_WAIT0();          // drain pending (empty) groups
    __syncthreads();     // pipeline buffers dead -> reuse dynsm
    const int bb = m0 >> 11, sbase = m0 & 2047;

    if (z == 1) {
        // K path: transposed stage [n][m] + ||k||^2 reduction.
        bf* kTs = (bf*)dynsm;                    // [128 n][136 pitch]
        float* sksum = (float*)(dynsm + 65536);  // [128][4]

        float rowsq[4][2];
        #pragma unroll
        for (int mi = 0; mi < 4; mi++) { rowsq[mi][0] = 0.f; rowsq[mi][1] = 0.f; }

        #pragma unroll
        for (int mi = 0; mi < 4; mi++) {
            #pragma unroll
            for (int half = 0; half < 2; half++) {
                int mloc = wm + mi*16 + g + half*8;
                #pragma unroll
                for (int nj = 0; nj < 4; nj++) {
                    int nloc = wn + nj*8 + 2*qd;
                    int n = n0 + nloc;
                    int h = n >> 6, d = n & 63;
                    float v0 = acc[mi][nj][half*2 + 0] + bias[h*Dd + d];
                    float v1 = acc[mi][nj][half*2 + 1] + bias[h*Dd + d + 1];
                    rowsq[mi][half] = fmaf(v0, v0, rowsq[mi][half]);
                    rowsq[mi][half] = fmaf(v1, v1, rowsq[mi][half]);
                    kTs[ nloc     *136 + mloc] = __float2bfloat16_rn(v0);
                    kTs[(nloc + 1)*136 + mloc] = __float2bfloat16_rn(v1);
                }
            }
        }
        #pragma unroll
        for (int mi = 0; mi < 4; mi++)
            #pragma unroll
            for (int half = 0; half < 2; half++) {
                float v = rowsq[mi][half];
                v += __shfl_xor_sync(0xffffffffu, v, 1);
                v += __shfl_xor_sync(0xffffffffu, v, 2);
                if (qd == 0)
                    sksum[(wm + mi*16 + g + half*8)*4 + (wid >> 1)] = v;
            }
        __syncthreads();

        // coalesced kT store: row r = (h_loc, d) -> 128 s-values contiguous
        #pragma unroll
        for (int u = 0; u < 8; u++) {
            int idx = u * 256 + tid;           // 0..2047
            int r = idx >> 4, c16 = (idx & 15) * 8;
            int h = (n0 >> 6) + (r >> 6), d = r & 63;
            uint4 v = *(uint4*)&kTs[r*136 + c16];
            *(uint4*)&g_kT[(((size_t)bb*Hh + h)*Dd + d)*Ss + sbase + c16] = v;
        }
        {
            int row = tid >> 1, hh = tid & 1;
            float v = sksum[row*4 + 2*hh] + sksum[row*4 + 2*hh + 1];
            int h = (n0 >> 6) + hh;
            g_sk[((size_t)bb*Hh + h)*Ss + sbase + row] = 0.5f * SCL2 * v;
        }
    } else {
        // Q/V path: direct-layout stage [m][n], then coalesced 16B d-run stores.
        bf* Qs = (bf*)dynsm;                     // [128 m][136 pitch]
        #pragma unroll
        for (int mi = 0; mi < 4; mi++) {
            #pragma unroll
            for (int half = 0; half < 2; half++) {
                int mloc = wm + mi*16 + g + half*8;
                #pragma unroll
                for (int nj = 0; nj < 4; nj++) {
                    int nloc = wn + nj*8 + 2*qd;
                    int n = n0 + nloc;
                    int h = n >> 6, d = n & 63;
                    float v0 = acc[mi][nj][half*2 + 0] + bias[h*Dd + d];
                    float v1 = acc[mi][nj][half*2 + 1] + bias[h*Dd + d + 1];
                    *(unsigned*)&Qs[mloc*136 + nloc] = f22bf(v0, v1);
                }
            }
        }
        __syncthreads();

        bf* out = (z == 0) ? g_q : g_v;
        #pragma unroll
        for (int u = 0; u < 8; u++) {
            int idx = u * 256 + tid;           // 0..2047 = 128 rows x 16 chunks
            int r = idx >> 4, c16 = (idx & 15) * 8;
            int h = (n0 >> 6) + (c16 >> 6), d = c16 & 63;
            int s = sbase + r;
            uint4 v = *(uint4*)&Qs[r*136 + c16];
            *(uint4*)&out[(((size_t)bb*Hh + h)*Ss + s)*Dd + d] = v;
        }
    }
}

// ---------------------------------------------------------------------------
// Kernel 2: flash attention, bf16 m16n8k16, fixed-max softmax (exp2 path),
// SPLIT-K (2).  BQ=64, 4 warps.  fp16 unnormalized partials + fp32 l.
// ---------------------------------------------------------------------------
__global__ __launch_bounds__(128) void flash_kernel()
{
    __shared__ __align__(16) unsigned char smbuf[40960];
    bf* Ks[2] = { (bf*)smbuf,            (bf*)(smbuf +  9216) };   // [64][72]
    bf* Vs[2] = { (bf*)(smbuf + 18432),  (bf*)(smbuf + 27648) };   // [64][72]
    float* sks = (float*)(smbuf + 36864);                          // [1024]

    const int bh = blockIdx.y;
    const int q0 = blockIdx.x * 64;
    const int ksp = blockIdx.z;
    const int kbase = ksp * (Ss / NSPLIT);
    const int tid = threadIdx.x;
    const int wid = tid >> 5, lane = tid & 31;
    const int g = lane >> 2, qd = lane & 3;

    const bf* Qg   = g_q  + ((size_t)bh * Ss + q0) * Dd;
    const bf* KTg  = g_kT + (size_t)bh * Dd * Ss;
    const bf* Vg   = g_v  + (size_t)bh * Ss * Dd;
    const float* skg = g_sk + (size_t)bh * Ss + kbase;

    const int arow_l = (lane & 7) + ((lane >> 3) & 1) * 8;
    const int acol_l = (lane >> 4) * 8;
    const int brow_l = (lane & 7) + ((lane >> 3) & 1) * 8;
    const int bcol_l = (lane >> 4) * 8;
    const int wrow = wid * 16;
    const int crow = wrow + g;

    const int ld_r  = tid >> 3;
    const int ld_c8 = (tid & 7) << 3;

    // ---- Prologue: Q -> staging (Ks[0]) -> A regs; this split's sk row ----
    {
        bf* Qst = Ks[0];
        #pragma unroll
        for (int u = 0; u < 4; u++)
            *(uint4*)&Qst[(ld_r + u*16)*72 + ld_c8] =
                *(const uint4*)(Qg + (size_t)(ld_r + u*16) * Dd + ld_c8);
        #pragma unroll
        for (int u = 0; u < 2; u++) {
            int idx = u * 128 + tid;
            *(float4*)&sks[idx*4] = *(const float4*)(skg + idx*4);
        }
        __syncthreads();
    }
    unsigned qa[4][4];
    #pragma unroll
    for (int t = 0; t < 4; t++)
        ldmA(qa[t], s2u(&Ks[0][(wrow + arow_l)*72 + t*16 + acol_l]));

    // row constants: 0.5*SCL2*||q||^2 for rows crow and crow+8
    float sq0 = 0.f, sq1 = 0.f;
    {
        const bf* r0 = &Ks[0][crow*72];
        const bf* r1 = &Ks[0][(crow+8)*72];
        #pragma unroll
        for (int d = 0; d < Dd; d++) {
            float v0 = __bfloat162float(r0[d]);
            float v1 = __bfloat162float(r1[d]);
            sq0 = fmaf(v0, v0, sq0);
            sq1 = fmaf(v1, v1, sq1);
        }
        sq0 *= 0.5f * SCL2;
        sq1 *= 0.5f * SCL2;
    }
    __syncthreads();   // Q staging dead; cp.async may overwrite

    auto issue_loads = [&](int buf, int k0) {
        #pragma unroll
        for (int u = 0; u < 4; u++) {
            int r = ld_r + u*16;
            cp16(s2u(&Ks[buf][r*72 + ld_c8]), KTg + (size_t)r * Ss + k0 + ld_c8);
            cp16(s2u(&Vs[buf][r*72 + ld_c8]), Vg  + (size_t)(k0 + r) * Dd + ld_c8);
        }
        CP_COMMIT();
    };
    issue_loads(0, kbase);

    float l0 = 0.f, l1 = 0.f;
    float oacc[8][4];
    #pragma unroll
    for (int j = 0; j < 8; j++)
        #pragma unroll
        for (int r = 0; r < 4; r++) oacc[j][r] = 0.f;

    const int NIT = (Ss / NSPLIT) / 64;   // 16
    for (int it = 0; it < NIT; it++) {
        const int k0 = kbase + it * 64;
        const int buf = it & 1;
        CP_WAIT0();
        __syncthreads();
        if (it + 1 < NIT) issue_loads(buf ^ 1, k0 + 64);

        // ---- scores: Q(reg) x K^T[d][key] ----
        float sc[8][4];
        #pragma unroll
        for (int j = 0; j < 8; j++)
            #pragma unroll
            for (int r = 0; r < 4; r++) sc[j][r] = 0.f;

        #pragma unroll
        for (int t = 0; t < 4; t++) {
            #pragma unroll
            for (int p = 0; p < 4; p++) {
                unsigned b[4];
                ldmB4(b, s2u(&Ks[buf][(t*16 + brow_l)*72 + p*16 + bcol_l]));
                mma_bf16(sc[2*p    ], qa[t], &b[0]);
                mma_bf16(sc[2*p + 1], qa[t], &b[2]);
            }
        }

        // ---- exact softmax, fixed max 0, exp2 path (sk/sq pre-scaled) ----
        #pragma unroll
        for (int j = 0; j < 8; j++) {
            #pragma unroll
            for (int c = 0; c < 2; c++) {
                float skc = sks[it*64 + j*8 + 2*qd + c];
                float p0 = exp2f(fmaf(sc[j][c],   SCL2, -skc) - sq0);
                float p1 = exp2f(fmaf(sc[j][2+c], SCL2, -skc) - sq1);
                sc[j][c]   = p0; l0 += p0;
                sc[j][2+c] = p1; l1 += p1;
            }
        }

        // ---- PV: P straight from registers (C-frag == A-frag layout) ----
        #pragma unroll
        for (int t = 0; t < 4; t++) {
            unsigned a[4];
            a[0] = f22bf(sc[2*t  ][0], sc[2*t  ][1]);
            a[1] = f22bf(sc[2*t  ][2], sc[2*t  ][3]);
            a[2] = f22bf(sc[2*t+1][0], sc[2*t+1][1]);
            a[3] = f22bf(sc[2*t+1][2], sc[2*t+1][3]);
            #pragma unroll
            for (int p = 0; p < 4; p++) {
                unsigned b[4];
                ldmB4(b, s2u(&Vs[buf][(t*16 + brow_l)*72 + p*16 + bcol_l]));
                mma_bf16(oacc[2*p    ], a, &b[0]);
                mma_bf16(oacc[2*p + 1], a, &b[2]);
            }
        }
    }

    // reduce l across the 4 qd lanes once
    l0 += __shfl_xor_sync(0xffffffffu, l0, 1);
    l0 += __shfl_xor_sync(0xffffffffu, l0, 2);
    l1 += __shfl_xor_sync(0xffffffffu, l1, 1);
    l1 += __shfl_xor_sync(0xffffffffu, l1, 2);

    // Epilogue: fp16 UNNORMALIZED partial out + fp32 l (combined in ln_kernel)
    const int s0 = q0 + crow, s1 = s0 + 8;
    __half* po = g_po + ((size_t)ksp * (Bb*Hh) + bh) * (Ss * Dd);
    #pragma unroll
    for (int j = 0; j < 8; j++) {
        int col = j*8 + 2*qd;
        *(__half2*)&po[(size_t)s0 * Dd + col] = __floats2half2_rn(oacc[j][0], oacc[j][1]);
        *(__half2*)&po[(size_t)s1 * Dd + col] = __floats2half2_rn(oacc[j][2], oacc[j][3]);
    }
    if (qd == 0) {
        float* pl = g_l + ((size_t)ksp * (Bb*Hh) + bh) * Ss;
        pl[s0] = l0;
        pl[s1] = l1;
    }
}

// ---------------------------------------------------------------------------
// Kernel 3: split-combine + residual add + custom LayerNorm.
// ---------------------------------------------------------------------------
__global__ __launch_bounds__(256) void ln_kernel(
    const float* __restrict__ resid, const float* __restrict__ gamma,
    const float* __restrict__ beta, float* __restrict__ out)
{
    const int row = blockIdx.x;            // b*2048 + s
    const int b = row >> 11, s = row & 2047;
    const int tid = threadIdx.x;
    const int h = tid >> 4;
    const int dv4 = (tid & 15) << 2;
    const size_t bh = (size_t)b * Hh + h;

    const __half* po0 = g_po + (bh                ) * (Ss * Dd) + (size_t)s * Dd + dv4;
    const __half* po1 = g_po + ((size_t)Bb*Hh + bh) * (Ss * Dd) + (size_t)s * Dd + dv4;
    float linv = 1.0f / (g_l[bh * Ss + s] + g_l[((size_t)Bb*Hh + bh) * Ss + s]);

    uint2 u0 = *(const uint2*)po0;         // 4 halves in one LDG.64
    uint2 u1 = *(const uint2*)po1;
    float2 a00 = __half22float2(*(__half2*)&u0.x);
    float2 a01 = __half22float2(*(__half2*)&u0.y);
    float2 a10 = __half22float2(*(__half2*)&u1.x);
    float2 a11 = __half22float2(*(__half2*)&u1.y);
    float4 r  = *(const float4*)(resid + (size_t)row * Ee + tid*4);
    float x0 = (a00.x + a10.x) * linv + r.x;
    float x1 = (a00.y + a10.y) * linv + r.y;
    float x2 = (a01.x + a11.x) * linv + r.z;
    float x3 = (a01.y + a11.y) * linv + r.w;

    float sum = x0 + x1 + x2 + x3;
    float sq  = x0*x0 + x1*x1 + x2*x2 + x3*x3;
    #pragma unroll
    for (int o = 16; o >= 1; o >>= 1) {
        sum += __shfl_xor_sync(0xffffffffu, sum, o);
        sq  += __shfl_xor_sync(0xffffffffu, sq,  o);
    }
    __shared__ float rs[8], rq[8];
    int w = tid >> 5, lane = tid & 31;
    if (lane == 0) { rs[w] = sum; rq[w] = sq; }
    __syncthreads();
    float ts = 0.f, tq = 0.f;
    #pragma unroll
    for (int i = 0; i < 8; i++) { ts += rs[i]; tq += rq[i]; }

    float mean = ts * (1.0f/1024.0f);
    float var  = (tq - 1024.0f * mean * mean) * (1.0f/1023.0f);  // ddof=1
    float stdv = sqrtf(var);

    float4 gv = *(const float4*)(gamma + tid*4);
    float4 bv = *(const float4*)(beta  + tid*4);
    float4 o4;
    o4.x = gv.x * (x0 - mean) / (stdv + 1e-6f + bv.x);
    o4.y = gv.y * (x1 - mean) / (stdv + 1e-6f + bv.y);
    o4.z = gv.z * (x2 - mean) / (stdv + 1e-6f + bv.z);
    o4.w = gv.w * (x3 - mean) / (stdv + 1e-6f + bv.w);
    *(float4*)(out + (size_t)row * Ee + tid*4) = o4;
}

// ---------------------------------------------------------------------------
// Launch.
// ---------------------------------------------------------------------------
extern "C" void kernel_launch(void* const* d_in, const int* in_sizes, int n_in,
                              void* d_out, int out_size)
{
    (void)in_sizes; (void)n_in; (void)out_size;
    const float* query = (const float*)d_in[0];
    const float* key   = (const float*)d_in[1];
    const float* value = (const float*)d_in[2];
    const float* resid = (const float*)d_in[3];
    const float* Wq = (const float*)d_in[4];
    const float* bq = (const float*)d_in[5];
    const float* Wk = (const float*)d_in[6];
    const float* bk = (const float*)d_in[7];
    const float* Wv = (const float*)d_in[8];
    const float* bv = (const float*)d_in[9];
    const float* gamma = (const float*)d_in[10];
    const float* beta  = (const float*)d_in[11];
    float* out = (float*)d_out;

    const int proj_smem = 3 * STAGE_BYTES;   // 107520
    cudaFuncSetAttribute(proj_kernel,
                         cudaFuncAttributeMaxDynamicSharedMemorySize, proj_smem);

    const int ncvt = (int)((3*NXE/4 + 3*NWE/4 + 255) / 256);
    cvt_kernel<<<ncvt, 256>>>(query, key, value, Wq, Wk, Wv);

    dim3 gproj(32, 8, 3);
    proj_kernel<<<gproj, 256, proj_smem>>>(bq, bk, bv);
    flash_kernel<<<dim3(32, 32, NSPLIT), 128>>>();
    ln_kernel<<<4096, 256>>>(resid, gamma, beta, out);
}